// round 15
// baseline (speedup 1.0000x reference)
#include <cuda_runtime.h>
#include <cuda_fp16.h>
#include <math.h>
#include <stdint.h>

// ---------------------------------------------------------------------------
// GPT-2 block, fp16 mma.sync + ldmatrix. R15: GEMMs use f16-accumulator MMA
// (m16n8k16.f16) within each K=64 chunk, spilled to f32 between chunks —
// tests the "f32-acc HMMA is half-rate on sm_100 legacy path" hypothesis.
// B=2, S=2048, D=1024, H=16, dh=64, INNER=4096
// ---------------------------------------------------------------------------

#define BATCH   2
#define SEQ     2048
#define DMODEL  1024
#define NHEADS  16
#define HDIM    64
#define INNER   4096
#define ROWS    (BATCH * SEQ)
#define EPS     1e-5f

// ------------------------- scratch (static device mem) ---------------------
__device__ __half g_x   [ROWS * DMODEL];
__device__ __half g_qkv [ROWS * 3 * DMODEL];
__device__ __half g_vT  [BATCH * NHEADS * HDIM * SEQ];
__device__ __half g_attn[ROWS * DMODEL];
__device__ float  g_h2  [ROWS * DMODEL];
__device__ __half g_y   [ROWS * DMODEL];
__device__ __half g_fc  [ROWS * INNER];
__device__ __half g_wT  [12 * 1024 * 1024];
#define WT_QKV_OFF  0
#define WT_PROJ_OFF (3072 * 1024)
#define WT_FC_OFF   (WT_PROJ_OFF + 1024 * 1024)
#define WT_MLP_OFF  (WT_FC_OFF + 4096 * 1024)

// ------------------------------ small helpers -------------------------------
__device__ __forceinline__ float gelu_exact(float x) {
    return 0.5f * x * (1.0f + erff(x * 0.70710678118654752f));
}

__device__ __forceinline__ uint32_t smem_u32(const void* p) {
    uint32_t a;
    asm("{ .reg .u64 t; cvta.to.shared.u64 t, %1; cvt.u32.u64 %0, t; }"
        : "=r"(a) : "l"(p));
    return a;
}

__device__ __forceinline__ void cpa16(uint32_t dst, const void* src) {
    asm volatile("cp.async.cg.shared.global [%0], [%1], 16;" :: "r"(dst), "l"(src));
}

__device__ __forceinline__ void mma_f16(
    float& c0, float& c1, float& c2, float& c3,
    uint32_t a0, uint32_t a1, uint32_t a2, uint32_t a3,
    uint32_t b0, uint32_t b1)
{
    asm volatile(
        "mma.sync.aligned.m16n8k16.row.col.f32.f16.f16.f32 "
        "{%0,%1,%2,%3}, {%4,%5,%6,%7}, {%8,%9}, {%0,%1,%2,%3};"
        : "+f"(c0), "+f"(c1), "+f"(c2), "+f"(c3)
        : "r"(a0), "r"(a1), "r"(a2), "r"(a3), "r"(b0), "r"(b1));
}

// f16-accumulator MMA: D/C packed half2 pairs (c0 = row gi cols {2t,2t+1},
// c1 = row gi+8). Same A/B fragments as the f32 form.
__device__ __forceinline__ void mma_f16acc(
    uint32_t& c0, uint32_t& c1,
    uint32_t a0, uint32_t a1, uint32_t a2, uint32_t a3,
    uint32_t b0, uint32_t b1)
{
    asm volatile(
        "mma.sync.aligned.m16n8k16.row.col.f16.f16.f16.f16 "
        "{%0,%1}, {%2,%3,%4,%5}, {%6,%7}, {%0,%1};"
        : "+r"(c0), "+r"(c1)
        : "r"(a0), "r"(a1), "r"(a2), "r"(a3), "r"(b0), "r"(b1));
}

__device__ __forceinline__ void hacc_spill(float* acc4, uint32_t c0, uint32_t c1)
{
    float2 lo = __half22float2(*(__half2*)&c0);
    float2 hi = __half22float2(*(__half2*)&c1);
    acc4[0] += lo.x; acc4[1] += lo.y;
    acc4[2] += hi.x; acc4[3] += hi.y;
}

__device__ __forceinline__ void ldsm4(
    uint32_t& r0, uint32_t& r1, uint32_t& r2, uint32_t& r3, uint32_t addr)
{
    asm volatile(
        "ldmatrix.sync.aligned.m8n8.x4.shared.b16 {%0,%1,%2,%3}, [%4];"
        : "=r"(r0), "=r"(r1), "=r"(r2), "=r"(r3) : "r"(addr));
}

// --------------------------- LayerNorm row body -----------------------------
__device__ __forceinline__ void ln_row(
    const float* __restrict__ in, const float* __restrict__ gamma,
    const float* __restrict__ beta, __half* __restrict__ out, int row)
{
    __shared__ float red[16];
    const int tid = threadIdx.x;
    const float* x = in + (size_t)row * DMODEL;

    float4 v = *(const float4*)(x + tid * 4);
    float s = v.x + v.y + v.z + v.w;
    float q = v.x * v.x + v.y * v.y + v.z * v.z + v.w * v.w;
    #pragma unroll
    for (int off = 16; off; off >>= 1) {
        s += __shfl_xor_sync(0xffffffffu, s, off);
        q += __shfl_xor_sync(0xffffffffu, q, off);
    }
    const int w = tid >> 5;
    if ((tid & 31) == 0) { red[w] = s; red[8 + w] = q; }
    __syncthreads();
    float st = 0.f, qt = 0.f;
    #pragma unroll
    for (int i = 0; i < 8; i++) { st += red[i]; qt += red[8 + i]; }

    const float mu  = st * (1.0f / DMODEL);
    const float var = qt * (1.0f / DMODEL) - mu * mu;
    const float inv = rsqrtf(var + EPS);

    float4 g = *(const float4*)(gamma + tid * 4);
    float4 b = *(const float4*)(beta  + tid * 4);
    __half2 p0 = __floats2half2_rn((v.x - mu) * inv * g.x + b.x,
                                   (v.y - mu) * inv * g.y + b.y);
    __half2 p1 = __floats2half2_rn((v.z - mu) * inv * g.z + b.z,
                                   (v.w - mu) * inv * g.w + b.w);
    uint2 pk;
    pk.x = *(uint32_t*)&p0;
    pk.y = *(uint32_t*)&p1;
    *(uint2*)(out + (size_t)row * DMODEL + tid * 4) = pk;
}

__global__ void __launch_bounds__(256) ln_kernel(
    const float* __restrict__ in, const float* __restrict__ gamma,
    const float* __restrict__ beta, __half* __restrict__ out)
{
    ln_row(in, gamma, beta, out, blockIdx.x);
}

// ---------------- fused prep: LN1 + 4 weight transposes ---------------------
__global__ void __launch_bounds__(256) prep_kernel(
    const float* __restrict__ hidden, const float* __restrict__ g1,
    const float* __restrict__ be1, __half* __restrict__ x,
    const float* __restrict__ w_qkv, const float* __restrict__ w_proj,
    const float* __restrict__ w_fc,  const float* __restrict__ w_mlp,
    __half* __restrict__ wT)
{
    const int bid = blockIdx.x;
    if (bid < ROWS) {
        ln_row(hidden, g1, be1, x, bid);
        return;
    }
    int t = bid - ROWS;
    const float* in;
    __half* outp;
    int K, N, bx, by;
    if (t < 3072)      { in = w_qkv;  outp = (__half*)wT + WT_QKV_OFF;
                         K = 1024; N = 3072; bx = t % 96;  by = t / 96; }
    else if (t < 4096) { t -= 3072; in = w_proj; outp = (__half*)wT + WT_PROJ_OFF;
                         K = 1024; N = 1024; bx = t % 32;  by = t / 32; }
    else if (t < 8192) { t -= 4096; in = w_fc;   outp = (__half*)wT + WT_FC_OFF;
                         K = 1024; N = 4096; bx = t % 128; by = t / 128; }
    else               { t -= 8192; in = w_mlp;  outp = (__half*)wT + WT_MLP_OFF;
                         K = 4096; N = 1024; bx = t % 32;  by = t / 32; }

    __shared__ float tt[32][33];
    const int n0 = bx * 32, k0 = by * 32;
    const int tx = threadIdx.x & 31;
    const int ty = threadIdx.x >> 5;
    #pragma unroll
    for (int i = 0; i < 32; i += 8)
        tt[ty + i][tx] = in[(size_t)(k0 + ty + i) * N + n0 + tx];
    __syncthreads();
    #pragma unroll
    for (int i = 0; i < 32; i += 8)
        outp[(size_t)(n0 + ty + i) * K + k0 + tx] = __float2half(tt[tx][ty + i]);
}

// ------------------------------ common defs ---------------------------------
#define EPI_QKV   0
#define EPI_RES   1
#define EPI_GELU  2

#define BKH      64
#define SPH      72
#define SPW      (SPH / 2)

// --------------- GEMM A: 128x128 tile, 2 CTA/SM (qkv / fc) ------------------
#define TILE_H   (128 * SPH)
#define STAGE_H  (2 * TILE_H)
#define GSTAGES  3
#define GSMEM_DYN (GSTAGES * STAGE_H * 2)   // 110592 B -> 2 CTAs/SM

template <int EPI>
__global__ void __launch_bounds__(512, 2) hgemm_kernel(
    const __half* __restrict__ A, const __half* __restrict__ Bt,
    const float* __restrict__ bias, const float* __restrict__ res,
    void* __restrict__ Cv, __half* __restrict__ vT, int M, int N, int K)
{
    extern __shared__ __half smh[];

    const int tid   = threadIdx.x;
    const int wid   = tid >> 5;
    const int lane  = tid & 31;
    const int gi    = lane >> 2;
    const int tig   = lane & 3;
    const int warpM = wid >> 2;
    const int warpN = wid & 3;

    const int mrow0 = blockIdx.y * 128;
    const int ncol0 = blockIdx.x * 128;

    const __half* Abase = A  + (size_t)mrow0 * K;
    const __half* Bbase = Bt + (size_t)ncol0 * K;

    const uint32_t smem_base = smem_u32(smh);

    const uint32_t aOff = (uint32_t)(
        (warpM * 32 + (lane & 7) + (((lane >> 3) & 1) << 3)) * SPH
        + ((lane >> 4) << 3)) * 2;
    const uint32_t bOff = (uint32_t)(
        (warpN * 32 + (lane & 7) + ((lane >> 4) << 3)) * SPH
        + (((lane >> 3) & 1) << 3)) * 2;

    float acc[2][4][4];
    #pragma unroll
    for (int i = 0; i < 2; i++)
        #pragma unroll
        for (int j = 0; j < 4; j++)
            #pragma unroll
            for (int q = 0; q < 4; q++) acc[i][j][q] = 0.f;

    const int NC = K / BKH;

    auto load_stage = [&](int c) {
        const int s = c % GSTAGES;
        const uint32_t a_st = smem_base + s * STAGE_H * 2;
        const uint32_t b_st = a_st + TILE_H * 2;
        const int kof = c * BKH;
        #pragma unroll
        for (int i = 0; i < 2; i++) {
            const int lin = tid + i * 512;
            const int r   = lin >> 3;
            const int cc  = lin & 7;
            const uint32_t off = (uint32_t)(r * (SPH * 2) + cc * 16);
            cpa16(a_st + off, Abase + (size_t)r * K + kof + cc * 8);
            cpa16(b_st + off, Bbase + (size_t)r * K + kof + cc * 8);
        }
    };

    #pragma unroll
    for (int p = 0; p < GSTAGES - 1; p++) {
        load_stage(p);
        asm volatile("cp.async.commit_group;" ::: "memory");
    }

    for (int c = 0; c < NC; c++) {
        asm volatile("cp.async.wait_group %0;" :: "n"(GSTAGES - 2) : "memory");
        __syncthreads();

        if (c + GSTAGES - 1 < NC) load_stage(c + GSTAGES - 1);
        asm volatile("cp.async.commit_group;" ::: "memory");

        const uint32_t stage_base = smem_base + (c % GSTAGES) * STAGE_H * 2;
        const uint32_t aAddr = stage_base + aOff;
        const uint32_t bAddr = stage_base + TILE_H * 2 + bOff;

        uint32_t hacc[2][4][2];
        #pragma unroll
        for (int i = 0; i < 2; i++)
            #pragma unroll
            for (int j = 0; j < 4; j++) { hacc[i][j][0] = 0u; hacc[i][j][1] = 0u; }

        #pragma unroll
        for (int ks = 0; ks < 4; ks++) {
            uint32_t af[2][4], bf[4][2];
            ldsm4(af[0][0], af[0][1], af[0][2], af[0][3], aAddr + ks * 32);
            ldsm4(af[1][0], af[1][1], af[1][2], af[1][3],
                  aAddr + 16 * SPH * 2 + ks * 32);
            ldsm4(bf[0][0], bf[0][1], bf[1][0], bf[1][1], bAddr + ks * 32);
            ldsm4(bf[2][0], bf[2][1], bf[3][0], bf[3][1],
                  bAddr + 16 * SPH * 2 + ks * 32);
            #pragma unroll
            for (int im = 0; im < 2; im++)
                #pragma unroll
                for (int jn = 0; jn < 4; jn++)
                    mma_f16acc(hacc[im][jn][0], hacc[im][jn][1],
                               af[im][0], af[im][1], af[im][2], af[im][3],
                               bf[jn][0], bf[jn][1]);
        }

        #pragma unroll
        for (int im = 0; im < 2; im++)
            #pragma unroll
            for (int jn = 0; jn < 4; jn++)
                hacc_spill(acc[im][jn], hacc[im][jn][0], hacc[im][jn][1]);
    }

    // ---- epilogue ----------------------------------------------------------
    const bool vpart = (EPI == EPI_QKV) && (ncol0 >= 2 * DMODEL);
    const bool qpart = (EPI == EPI_QKV) && (ncol0 < DMODEL);
    #pragma unroll
    for (int im = 0; im < 2; im++) {
        const int r0 = mrow0 + warpM * 32 + im * 16 + gi;
        #pragma unroll
        for (int hf = 0; hf < 2; hf++) {
            const size_t row = (size_t)(r0 + hf * 8);
            #pragma unroll
            for (int jn = 0; jn < 4; jn++) {
                const int col = ncol0 + warpN * 32 + jn * 8 + tig * 2;
                float ox = acc[im][jn][hf * 2 + 0];
                float oy = acc[im][jn][hf * 2 + 1];
                float2 bv = *(const float2*)(bias + col);
                ox += bv.x; oy += bv.y;
                if (EPI == EPI_RES) {
                    float2 rv = *(const float2*)(res + row * N + col);
                    float2 o2 = {ox + rv.x, oy + rv.y};
                    *(float2*)((float*)Cv + row * N + col) = o2;
                } else if (EPI == EPI_GELU) {
                    __half2 hv = __floats2half2_rn(gelu_exact(ox), gelu_exact(oy));
                    *(__half2*)((__half*)Cv + row * N + col) = hv;
                } else {  // EPI_QKV
                    if (vpart) {
                        const int vcol = col - 2 * DMODEL;
                        const int hh = vcol >> 6, d = vcol & 63;
                        const int bb = (int)(row >> 11), tok = (int)(row & 2047);
                        __half* vp = vT +
                            ((size_t)((bb * NHEADS + hh) * HDIM + d)) * SEQ + tok;
                        vp[0]   = __float2half(ox);
                        vp[SEQ] = __float2half(oy);
                    } else {
                        if (qpart) { ox *= 0.125f; oy *= 0.125f; }  // exact 2^-3
                        __half2 hv = __floats2half2_rn(ox, oy);
                        *(__half2*)((__half*)Cv + row * N + col) = hv;
                    }
                }
            }
        }
    }
}

// --------------- GEMM B: 256x128 tile, 1 CTA/SM (proj / mlp) ----------------
#define A_TILE_H (256 * SPH)
#define B_TILE_H (128 * SPH)
#define STAGE2_H (A_TILE_H + B_TILE_H)
#define GSMEM2_DYN (GSTAGES * STAGE2_H * 2)   // 165888 B -> 1 CTA/SM

template <int EPI>
__global__ void __launch_bounds__(512, 1) hgemm256_kernel(
    const __half* __restrict__ A, const __half* __restrict__ Bt,
    const float* __restrict__ bias, const float* __restrict__ res,
    void* __restrict__ Cv, int M, int N, int K)
{
    extern __shared__ __half smh[];

    const int tid   = threadIdx.x;
    const int wid   = tid >> 5;
    const int lane  = tid & 31;
    const int gi    = lane >> 2;
    const int tig   = lane & 3;
    const int warpM = wid >> 2;
    const int warpN = wid & 3;

    const int mrow0 = blockIdx.y * 256;
    const int ncol0 = blockIdx.x * 128;

    const __half* Abase = A  + (size_t)mrow0 * K;
    const __half* Bbase = Bt + (size_t)ncol0 * K;

    const uint32_t smem_base = smem_u32(smh);

    const uint32_t aOff = (uint32_t)(
        (warpM * 64 + (lane & 7) + (((lane >> 3) & 1) << 3)) * SPH
        + ((lane >> 4) << 3)) * 2;
    const uint32_t bOff = (uint32_t)(
        (warpN * 32 + (lane & 7) + ((lane >> 4) << 3)) * SPH
        + (((lane >> 3) & 1) << 3)) * 2;

    float acc[4][4][4];
    #pragma unroll
    for (int i = 0; i < 4; i++)
        #pragma unroll
        for (int j = 0; j < 4; j++)
            #pragma unroll
            for (int q = 0; q < 4; q++) acc[i][j][q] = 0.f;

    const int NC = K / BKH;

    auto load_stage = [&](int c) {
        const int s = c % GSTAGES;
        const uint32_t a_st = smem_base + s * STAGE2_H * 2;
        const uint32_t b_st = a_st + A_TILE_H * 2;
        const int kof = c * BKH;
        #pragma unroll
        for (int i = 0; i < 6; i++) {
            const int lin = tid + i * 512;
            if (lin < 2048) {
                const int r  = lin >> 3;
                const int cc = lin & 7;
                const uint32_t off = (uint32_t)(r * (SPH * 2) + cc * 16);
                cpa16(a_st + off, Abase + (size_t)r * K + kof + cc * 8);
            } else {
                const int j  = lin - 2048;
                const int r  = j >> 3;
                const int cc = j & 7;
                const uint32_t off = (uint32_t)(r * (SPH * 2) + cc * 16);
                cpa16(b_st + off, Bbase + (size_t)r * K + kof + cc * 8);
            }
        }
    };

    #pragma unroll
    for (int p = 0; p < GSTAGES - 1; p++) {
        load_stage(p);
        asm volatile("cp.async.commit_group;" ::: "memory");
    }

    for (int c = 0; c < NC; c++) {
        asm volatile("cp.async.wait_group %0;" :: "n"(GSTAGES - 2) : "memory");
        __syncthreads();

        if (c + GSTAGES - 1 < NC) load_stage(c + GSTAGES - 1);
        asm volatile("cp.async.commit_group;" ::: "memory");

        const uint32_t stage_base = smem_base + (c % GSTAGES) * STAGE2_H * 2;
        const uint32_t aAddr = stage_base + aOff;
        const uint32_t bAddr = stage_base + A_TILE_H * 2 + bOff;

        uint32_t hacc[4][4][2];
        #pragma unroll
        for (int i = 0; i < 4; i++)
            #pragma unroll
            for (int j = 0; j < 4; j++) { hacc[i][j][0] = 0u; hacc[i][j][1] = 0u; }

        #pragma unroll
        for (int ks = 0; ks < 4; ks++) {
            uint32_t af[4][4], bf[4][2];
            #pragma unroll
            for (int im = 0; im < 4; im++)
                ldsm4(af[im][0], af[im][1], af[im][2], af[im][3],
                      aAddr + im * (16 * SPH * 2) + ks * 32);
            ldsm4(bf[0][0], bf[0][1], bf[1][0], bf[1][1], bAddr + ks * 32);
            ldsm4(bf[2][0], bf[2][1], bf[3][0], bf[3][1],
                  bAddr + 16 * SPH * 2 + ks * 32);
            #pragma unroll
            for (int im = 0; im < 4; im++)
                #pragma unroll
                for (int jn = 0; jn < 4; jn++)
                    mma_f16acc(hacc[im][jn][0], hacc[im][jn][1],
                               af[im][0], af[im][1], af[im][2], af[im][3],
                               bf[jn][0], bf[jn][1]);
        }

        #pragma unroll
        for (int im = 0; im < 4; im++)
            #pragma unroll
            for (int jn = 0; jn < 4; jn++)
                hacc_spill(acc[im][jn], hacc[im][jn][0], hacc[im][jn][1]);
    }

    // ---- epilogue (EPI_RES only) -------------------------------------------
    #pragma unroll
    for (int im = 0; im < 4; im++) {
        const int r0 = mrow0 + warpM * 64 + im * 16 + gi;
        #pragma unroll
        for (int hf = 0; hf < 2; hf++) {
            const size_t row = (size_t)(r0 + hf * 8);
            #pragma unroll
            for (int jn = 0; jn < 4; jn++) {
                const int col = ncol0 + warpN * 32 + jn * 8 + tig * 2;
                float ox = acc[im][jn][hf * 2 + 0];
                float oy = acc[im][jn][hf * 2 + 1];
                float2 bv = *(const float2*)(bias + col);
                ox += bv.x; oy += bv.y;
                float2 rv = *(const float2*)(res + row * N + col);
                float2 o2 = {ox + rv.x, oy + rv.y};
                *(float2*)((float*)Cv + row * N + col) = o2;
            }
        }
    }
}

// ------------------------- Flash attention (fp16 MMA) -----------------------
// 128 q-rows per CTA, f32-acc MMA (unchanged from R14).
#define KVH    (64 * SPH)
#define P_OFF  (4 * KVH)
#define ATTN_SMEM_B ((4 * KVH + 128 * SPH) * 2)   // 55296 B

__global__ void __launch_bounds__(256, 2) attn_kernel(
    const __half* __restrict__ qkv, const __half* __restrict__ vT,
    __half* __restrict__ out)
{
    extern __shared__ __half smh[];
    const uint32_t smem_base = smem_u32(smh);

    const int qt  = (int)gridDim.x - 1 - (int)blockIdx.x;
    const int b   = blockIdx.y >> 4;
    const int h   = blockIdx.y & 15;
    const int tid = threadIdx.x;
    const int wid = tid >> 5;
    const int lane = tid & 31;
    const int gi  = lane >> 2;
    const int tig = lane & 3;

    const int q0 = qt * 128;
    const int qrow_w = q0 + wid * 16;
    const int nkt = qt * 2 + 2;

    const uint32_t nkOff = (uint32_t)(
        ((lane & 7) + ((lane >> 4) << 3)) * SPH
        + (((lane >> 3) & 1) << 3)) * 2;
    const uint32_t pOff = (uint32_t)(
        (wid * 16 + (lane & 7) + (((lane >> 3) & 1) << 3)) * SPH
        + ((lane >> 4) << 3)) * 2;

    auto load_tile = [&](int kt) {
        const int st = kt & 1;
        const __half* Kg = qkv + ((size_t)(b * SEQ + kt * 64)) * 3072
                           + DMODEL + h * HDIM;
        const __half* Vg = vT + ((size_t)((b * NHEADS + h) * HDIM)) * SEQ + kt * 64;
        const uint32_t Kd = smem_base + st * (KVH * 2);
        const uint32_t Vd = smem_base + (2 + st) * (KVH * 2);
        #pragma unroll
        for (int i = 0; i < 4; i++) {
            const int idx = tid + i * 256;
            if (idx < 512) {
                const int r = idx >> 3, cc = idx & 7;
                cpa16(Kd + r * (SPH * 2) + cc * 16, Kg + (size_t)r * 3072 + cc * 8);
            } else {
                const int j = idx - 512;
                const int r = j >> 3, cc = j & 7;
                cpa16(Vd + r * (SPH * 2) + cc * 16, Vg + (size_t)r * SEQ + cc * 8);
            }
        }
    };

    {
        const __half* Qg = qkv + ((size_t)(b * SEQ + q0)) * 3072 + h * HDIM;
        const uint32_t Pd = smem_base + P_OFF * 2;
        #pragma unroll
        for (int i = 0; i < 4; i++) {
            const int idx = tid + i * 256;
            const int r = idx >> 3, cc = idx & 7;
            cpa16(Pd + r * (SPH * 2) + cc * 16, Qg + (size_t)r * 3072 + cc * 8);
        }
        asm volatile("cp.async.commit_group;" ::: "memory");
        load_tile(0);
        asm volatile("cp.async.commit_group;" ::: "memory");
        asm volatile("cp.async.wait_group 0;" ::: "memory");
        __syncthreads();
    }

    uint32_t qf[4][4];
    {
        const uint32_t qAddr = smem_base + P_OFF * 2 + pOff;
        #pragma unroll
        for (int ks = 0; ks < 4; ks++)
            ldsm4(qf[ks][0], qf[ks][1], qf[ks][2], qf[ks][3], qAddr + ks * 32);
    }

    float m[2] = {-1e30f, -1e30f};
    float l[2] = {0.f, 0.f};
    float o[8][4];
    #pragma unroll
    for (int jn = 0; jn < 8; jn++)
        #pragma unroll
        for (int q = 0; q < 4; q++) o[jn][q] = 0.f;

    for (int kt = 0; kt < nkt; kt++) {
        if (kt > 0) {
            asm volatile("cp.async.wait_group 0;" ::: "memory");
            __syncthreads();
        }
        if (kt + 1 < nkt) {
            load_tile(kt + 1);
            asm volatile("cp.async.commit_group;" ::: "memory");
        }

        const int st = kt & 1;
        const uint32_t kAddr = smem_base + st * (KVH * 2) + nkOff;
        const uint32_t vAddr = smem_base + (2 + st) * (KVH * 2) + nkOff;

        float s[8][4];
        #pragma unroll
        for (int jn = 0; jn < 8; jn++)
            #pragma unroll
            for (int q = 0; q < 4; q++) s[jn][q] = 0.f;

        #pragma unroll
        for (int ks = 0; ks < 4; ks++) {
            uint32_t bf[8][2];
            #pragma unroll
            for (int jnp = 0; jnp < 4; jnp++)
                ldsm4(bf[2 * jnp][0], bf[2 * jnp][1],
                      bf[2 * jnp + 1][0], bf[2 * jnp + 1][1],
                      kAddr + jnp * (16 * SPH * 2) + ks * 32);
            #pragma unroll
            for (int jn = 0; jn < 8; jn++)
                mma_f16(s[jn][0], s[jn][1], s[jn][2], s[jn][3],
                        qf[ks][0], qf[ks][1], qf[ks][2], qf[ks][3],
                        bf[jn][0], bf[jn][1]);
        }

        if (kt * 64 + 63 > qrow_w) {
            #pragma unroll
            for (int jn = 0; jn < 8; jn++) {
                const int kc = kt * 64 + jn * 8 + tig * 2;
                const int r0 = qrow_w + gi;
                const int r1 = r0 + 8;
                if (kc     > r0) s[jn][0] = -1e30f;
                if (kc + 1 > r0) s[jn][1] = -1e30f;
                if (kc     > r1) s[jn][2] = -1e30f;
                if (kc + 1 > r1) s[jn][3] = -1e30f;
            }
        }

        #pragma unroll
        for (int rr = 0; rr < 2; rr++) {
            const int i0 = rr * 2, i1 = rr * 2 + 1;
            float mx = -1e30f;
            #pragma unroll
            for (int jn = 0; jn < 8; jn++)
                mx = fmaxf(mx, fmaxf(s[jn][i0], s[jn][i1]));
            mx = fmaxf(mx, __shfl_xor_sync(0xffffffffu, mx, 1));
            mx = fmaxf(mx, __shfl_xor_sync(0xffffffffu, mx, 2));
            const float mn = fmaxf(m[rr], mx);
            const float al = __expf(m[rr] - mn);
            float rs = 0.f;
            #pragma unroll
            for (int jn = 0; jn < 8; jn++) {
                const float e0 = __expf(s[jn][i0] - mn);
                const float e1 = __expf(s[jn][i1] - mn);
                s[jn][i0] = e0; s[jn][i1] = e1;
                rs += e0 + e1;
            }
            rs += __shfl_xor_sync(0xffffffffu, rs, 1);
            rs += __shfl_xor_sync(0xffffffffu, rs, 2);
            l[rr] = l[rr] * al + rs;
            m[rr] = mn;
            #pragma unroll
            for (int jn = 0; jn < 8; jn++) { o[jn][i0] *= al; o[jn][i1] *= al; }
        }

        {
            uint32_t* Pst = (uint32_t*)(smh + P_OFF) + (wid * 16 + gi) * SPW;
            #pragma unroll
            for (int jn = 0; jn < 8; jn++) {
                __half2 p0 = __floats2half2_rn(s[jn][0], s[jn][1]);
                __half2 p1 = __floats2half2_rn(s[jn][2], s[jn][3]);
                Pst[jn * 4 + tig]           = *(uint32_t*)&p0;
                Pst[8 * SPW + jn * 4 + tig] = *(uint32_t*)&p1;
            }
        }
        __syncwarp();

        const uint32_t pAddr = smem_base + P_OFF * 2 + pOff;
        #pragma unroll
        for (int ks = 0; ks < 4; ks++) {
            uint32_t a0, a1, a2, a3;
            ldsm4(a0, a1, a2, a3, pAddr + ks * 32);
            uint32_t vf[8][2];
            #pragma unroll
            for (int jnp = 0; jnp < 4; jnp++)
                ldsm4(vf[2 * jnp][0], vf[2 * jnp][1],
                      vf[2 * jnp + 1][0], vf[2 * jnp + 1][1],
                      vAddr + jnp * (16 * SPH * 2) + ks * 32);
            #pragma unroll
            for (int jn = 0; jn < 8; jn++)
                mma_f16(o[jn][0], o[jn][1], o[jn][2], o[jn][3],
                        a0, a1, a2, a3, vf[jn][0], vf[jn][1]);
        }
        __syncwarp();
    }

    const float inv0 = 1.0f / l[0];
    const float inv1 = 1.0f / l[1];
    __half* O0 = out + ((size_t)(b * SEQ) + qrow_w + gi)     * DMODEL + h * HDIM;
    __half* O1 = out + ((size_t)(b * SEQ) + qrow_w + gi + 8) * DMODEL + h * HDIM;
    #pragma unroll
    for (int jn = 0; jn < 8; jn++) {
        __half2 v0 = __floats2half2_rn(o[jn][0] * inv0, o[jn][1] * inv0);
        __half2 v1 = __floats2half2_rn(o[jn][2] * inv1, o[jn][3] * inv1);
        *(__half2*)(O0 + jn * 8 + tig * 2) = v0;
        *(__half2*)(O1 + jn * 8 + tig * 2) = v1;
    }
}

// ------------------------------- launcher -----------------------------------
extern "C" void kernel_launch(void* const* d_in, const int* in_sizes, int n_in,
                              void* d_out, int out_size)
{
    const float* hidden = (const float*)d_in[0];
    const float* w_qkv  = (const float*)d_in[1];
    const float* b_qkv  = (const float*)d_in[2];
    const float* g1     = (const float*)d_in[3];
    const float* be1    = (const float*)d_in[4];
    const float* w_proj = (const float*)d_in[5];
    const float* b_proj = (const float*)d_in[6];
    const float* g2     = (const float*)d_in[7];
    const float* be2    = (const float*)d_in[8];
    const float* w_fc   = (const float*)d_in[9];
    const float* b_fc   = (const float*)d_in[10];
    const float* w_mlp  = (const float*)d_in[11];
    const float* b_mlp  = (const float*)d_in[12];
    float* out = (float*)d_out;

    __half *x, *qkv, *vT, *attn, *y, *fc, *wT;
    float  *h2;
    cudaGetSymbolAddress((void**)&x,    g_x);
    cudaGetSymbolAddress((void**)&qkv,  g_qkv);
    cudaGetSymbolAddress((void**)&vT,   g_vT);
    cudaGetSymbolAddress((void**)&attn, g_attn);
    cudaGetSymbolAddress((void**)&h2,   g_h2);
    cudaGetSymbolAddress((void**)&y,    g_y);
    cudaGetSymbolAddress((void**)&fc,   g_fc);
    cudaGetSymbolAddress((void**)&wT,   g_wT);

    __half* wT_qkv  = wT + WT_QKV_OFF;
    __half* wT_proj = wT + WT_PROJ_OFF;
    __half* wT_fc   = wT + WT_FC_OFF;
    __half* wT_mlp  = wT + WT_MLP_OFF;

    cudaFuncSetAttribute(attn_kernel,
                         cudaFuncAttributeMaxDynamicSharedMemorySize, ATTN_SMEM_B);
    cudaFuncSetAttribute(hgemm_kernel<EPI_QKV>,
                         cudaFuncAttributeMaxDynamicSharedMemorySize, GSMEM_DYN);
    cudaFuncSetAttribute(hgemm_kernel<EPI_GELU>,
                         cudaFuncAttributeMaxDynamicSharedMemorySize, GSMEM_DYN);
    cudaFuncSetAttribute(hgemm256_kernel<EPI_RES>,
                         cudaFuncAttributeMaxDynamicSharedMemorySize, GSMEM2_DYN);

    // 1. prep: LN1 + all 4 weight transposes in one launch
    prep_kernel<<<ROWS + 12288, 256>>>(hidden, g1, be1, x,
                                       w_qkv, w_proj, w_fc, w_mlp, wT);
    // 2. QKV (Q pre-scaled 1/8; K -> qkv half; V -> vT transposed)
    hgemm_kernel<EPI_QKV><<<dim3(3 * DMODEL / 128, ROWS / 128), 512, GSMEM_DYN>>>(
        x, wT_qkv, b_qkv, nullptr, qkv, vT, ROWS, 3 * DMODEL, DMODEL);
    // 3. attention -> half
    attn_kernel<<<dim3(SEQ / 128, BATCH * NHEADS), 256, ATTN_SMEM_B>>>(qkv, vT, attn);
    // 4. h2 = attn @ w_proj + b_proj + hidden  (f32)  [256-row tiles]
    hgemm256_kernel<EPI_RES><<<dim3(DMODEL / 128, ROWS / 256), 512, GSMEM2_DYN>>>(
        attn, wT_proj, b_proj, hidden, h2, ROWS, DMODEL, DMODEL);
    // 5. LN2 -> half
    ln_kernel<<<ROWS, 256>>>(h2, g2, be2, y);
    // 6. fc = gelu(y @ w_fc + b_fc) -> half
    hgemm_kernel<EPI_GELU><<<dim3(INNER / 128, ROWS / 128), 512, GSMEM_DYN>>>(
        y, wT_fc, b_fc, nullptr, fc, nullptr, ROWS, INNER, DMODEL);
    // 7. out = fc @ w_mlp + b_mlp + h2  (f32)  [256-row tiles]
    hgemm256_kernel<EPI_RES><<<dim3(DMODEL / 128, ROWS / 256), 512, GSMEM2_DYN>>>(
        fc, wT_mlp, b_mlp, h2, out, ROWS, DMODEL, INNER);
}

// round 16
// speedup vs baseline: 1.2030x; 1.2030x over previous
#include <cuda_runtime.h>
#include <cuda_fp16.h>
#include <math.h>
#include <stdint.h>

// ---------------------------------------------------------------------------
// GPT-2 block, fp16 mma.sync + ldmatrix. R16: R14 (best) + vectorized weight
// transpose (float4 load -> smem transpose -> half4 store, 4x fewer LSU ops).
// B=2, S=2048, D=1024, H=16, dh=64, INNER=4096
// ---------------------------------------------------------------------------

#define BATCH   2
#define SEQ     2048
#define DMODEL  1024
#define NHEADS  16
#define HDIM    64
#define INNER   4096
#define ROWS    (BATCH * SEQ)
#define EPS     1e-5f

// ------------------------- scratch (static device mem) ---------------------
__device__ __half g_x   [ROWS * DMODEL];
__device__ __half g_qkv [ROWS * 3 * DMODEL];
__device__ __half g_vT  [BATCH * NHEADS * HDIM * SEQ];
__device__ __half g_attn[ROWS * DMODEL];
__device__ float  g_h2  [ROWS * DMODEL];
__device__ __half g_y   [ROWS * DMODEL];
__device__ __half g_fc  [ROWS * INNER];
__device__ __half g_wT  [12 * 1024 * 1024];
#define WT_QKV_OFF  0
#define WT_PROJ_OFF (3072 * 1024)
#define WT_FC_OFF   (WT_PROJ_OFF + 1024 * 1024)
#define WT_MLP_OFF  (WT_FC_OFF + 4096 * 1024)

// ------------------------------ small helpers -------------------------------
__device__ __forceinline__ float gelu_exact(float x) {
    return 0.5f * x * (1.0f + erff(x * 0.70710678118654752f));
}

__device__ __forceinline__ uint32_t smem_u32(const void* p) {
    uint32_t a;
    asm("{ .reg .u64 t; cvta.to.shared.u64 t, %1; cvt.u32.u64 %0, t; }"
        : "=r"(a) : "l"(p));
    return a;
}

__device__ __forceinline__ void cpa16(uint32_t dst, const void* src) {
    asm volatile("cp.async.cg.shared.global [%0], [%1], 16;" :: "r"(dst), "l"(src));
}

__device__ __forceinline__ void mma_f16(
    float& c0, float& c1, float& c2, float& c3,
    uint32_t a0, uint32_t a1, uint32_t a2, uint32_t a3,
    uint32_t b0, uint32_t b1)
{
    asm volatile(
        "mma.sync.aligned.m16n8k16.row.col.f32.f16.f16.f32 "
        "{%0,%1,%2,%3}, {%4,%5,%6,%7}, {%8,%9}, {%0,%1,%2,%3};"
        : "+f"(c0), "+f"(c1), "+f"(c2), "+f"(c3)
        : "r"(a0), "r"(a1), "r"(a2), "r"(a3), "r"(b0), "r"(b1));
}

__device__ __forceinline__ void ldsm4(
    uint32_t& r0, uint32_t& r1, uint32_t& r2, uint32_t& r3, uint32_t addr)
{
    asm volatile(
        "ldmatrix.sync.aligned.m8n8.x4.shared.b16 {%0,%1,%2,%3}, [%4];"
        : "=r"(r0), "=r"(r1), "=r"(r2), "=r"(r3) : "r"(addr));
}

// --------------------------- LayerNorm row body -----------------------------
__device__ __forceinline__ void ln_row(
    const float* __restrict__ in, const float* __restrict__ gamma,
    const float* __restrict__ beta, __half* __restrict__ out, int row)
{
    __shared__ float red[16];
    const int tid = threadIdx.x;
    const float* x = in + (size_t)row * DMODEL;

    float4 v = *(const float4*)(x + tid * 4);
    float s = v.x + v.y + v.z + v.w;
    float q = v.x * v.x + v.y * v.y + v.z * v.z + v.w * v.w;
    #pragma unroll
    for (int off = 16; off; off >>= 1) {
        s += __shfl_xor_sync(0xffffffffu, s, off);
        q += __shfl_xor_sync(0xffffffffu, q, off);
    }
    const int w = tid >> 5;
    if ((tid & 31) == 0) { red[w] = s; red[8 + w] = q; }
    __syncthreads();
    float st = 0.f, qt = 0.f;
    #pragma unroll
    for (int i = 0; i < 8; i++) { st += red[i]; qt += red[8 + i]; }

    const float mu  = st * (1.0f / DMODEL);
    const float var = qt * (1.0f / DMODEL) - mu * mu;
    const float inv = rsqrtf(var + EPS);

    float4 g = *(const float4*)(gamma + tid * 4);
    float4 b = *(const float4*)(beta  + tid * 4);
    __half2 p0 = __floats2half2_rn((v.x - mu) * inv * g.x + b.x,
                                   (v.y - mu) * inv * g.y + b.y);
    __half2 p1 = __floats2half2_rn((v.z - mu) * inv * g.z + b.z,
                                   (v.w - mu) * inv * g.w + b.w);
    uint2 pk;
    pk.x = *(uint32_t*)&p0;
    pk.y = *(uint32_t*)&p1;
    *(uint2*)(out + (size_t)row * DMODEL + tid * 4) = pk;
}

__global__ void __launch_bounds__(256) ln_kernel(
    const float* __restrict__ in, const float* __restrict__ gamma,
    const float* __restrict__ beta, __half* __restrict__ out)
{
    ln_row(in, gamma, beta, out, blockIdx.x);
}

// ---------------- fused prep: LN1 + 4 weight transposes ---------------------
// Transpose: 32x32 tile, vectorized (1x float4 load + 1x 8B half4 store per
// thread), conflict-free scatter into pad-33 smem.
__global__ void __launch_bounds__(256) prep_kernel(
    const float* __restrict__ hidden, const float* __restrict__ g1,
    const float* __restrict__ be1, __half* __restrict__ x,
    const float* __restrict__ w_qkv, const float* __restrict__ w_proj,
    const float* __restrict__ w_fc,  const float* __restrict__ w_mlp,
    __half* __restrict__ wT)
{
    const int bid = blockIdx.x;
    if (bid < ROWS) {
        ln_row(hidden, g1, be1, x, bid);
        return;
    }
    int t = bid - ROWS;
    const float* in;
    __half* outp;
    int K, N, bx, by;
    if (t < 3072)      { in = w_qkv;  outp = (__half*)wT + WT_QKV_OFF;
                         K = 1024; N = 3072; bx = t % 96;  by = t / 96; }
    else if (t < 4096) { t -= 3072; in = w_proj; outp = (__half*)wT + WT_PROJ_OFF;
                         K = 1024; N = 1024; bx = t % 32;  by = t / 32; }
    else if (t < 8192) { t -= 4096; in = w_fc;   outp = (__half*)wT + WT_FC_OFF;
                         K = 1024; N = 4096; bx = t % 128; by = t / 128; }
    else               { t -= 8192; in = w_mlp;  outp = (__half*)wT + WT_MLP_OFF;
                         K = 4096; N = 1024; bx = t % 32;  by = t / 32; }

    __shared__ float t2[32][33];
    const int n0 = bx * 32, k0 = by * 32;
    const int tid = threadIdx.x;
    const int lr = tid >> 3;        // 0..31
    const int lc = tid & 7;         // 0..7

    // load: in[k0+lr][n0 + lc*4 .. +3], scatter transposed into smem
    float4 v4 = *(const float4*)(in + (size_t)(k0 + lr) * N + n0 + lc * 4);
    t2[lc * 4 + 0][lr] = v4.x;
    t2[lc * 4 + 1][lr] = v4.y;
    t2[lc * 4 + 2][lr] = v4.z;
    t2[lc * 4 + 3][lr] = v4.w;
    __syncthreads();

    // store: out[n0+lr][k0 + lc*4 .. +3] as one 8-byte half4
    __half2 h0 = __floats2half2_rn(t2[lr][lc * 4 + 0], t2[lr][lc * 4 + 1]);
    __half2 h1 = __floats2half2_rn(t2[lr][lc * 4 + 2], t2[lr][lc * 4 + 3]);
    uint2 pk2;
    pk2.x = *(uint32_t*)&h0;
    pk2.y = *(uint32_t*)&h1;
    *(uint2*)(outp + (size_t)(n0 + lr) * K + k0 + lc * 4) = pk2;
}

// ------------------------------ common defs ---------------------------------
#define EPI_QKV   0
#define EPI_RES   1
#define EPI_GELU  2

#define BKH      64
#define SPH      72
#define SPW      (SPH / 2)

// --------------- GEMM A: 128x128 tile, 2 CTA/SM (qkv / fc) ------------------
#define TILE_H   (128 * SPH)
#define STAGE_H  (2 * TILE_H)
#define GSTAGES  3
#define GSMEM_DYN (GSTAGES * STAGE_H * 2)   // 110592 B -> 2 CTAs/SM

template <int EPI>
__global__ void __launch_bounds__(512, 2) hgemm_kernel(
    const __half* __restrict__ A, const __half* __restrict__ Bt,
    const float* __restrict__ bias, const float* __restrict__ res,
    void* __restrict__ Cv, __half* __restrict__ vT, int M, int N, int K)
{
    extern __shared__ __half smh[];

    const int tid   = threadIdx.x;
    const int wid   = tid >> 5;
    const int lane  = tid & 31;
    const int gi    = lane >> 2;
    const int tig   = lane & 3;
    const int warpM = wid >> 2;
    const int warpN = wid & 3;

    const int mrow0 = blockIdx.y * 128;
    const int ncol0 = blockIdx.x * 128;

    const __half* Abase = A  + (size_t)mrow0 * K;
    const __half* Bbase = Bt + (size_t)ncol0 * K;

    const uint32_t smem_base = smem_u32(smh);

    const uint32_t aOff = (uint32_t)(
        (warpM * 32 + (lane & 7) + (((lane >> 3) & 1) << 3)) * SPH
        + ((lane >> 4) << 3)) * 2;
    const uint32_t bOff = (uint32_t)(
        (warpN * 32 + (lane & 7) + ((lane >> 4) << 3)) * SPH
        + (((lane >> 3) & 1) << 3)) * 2;

    float acc[2][4][4];
    #pragma unroll
    for (int i = 0; i < 2; i++)
        #pragma unroll
        for (int j = 0; j < 4; j++)
            #pragma unroll
            for (int q = 0; q < 4; q++) acc[i][j][q] = 0.f;

    const int NC = K / BKH;

    auto load_stage = [&](int c) {
        const int s = c % GSTAGES;
        const uint32_t a_st = smem_base + s * STAGE_H * 2;
        const uint32_t b_st = a_st + TILE_H * 2;
        const int kof = c * BKH;
        #pragma unroll
        for (int i = 0; i < 2; i++) {
            const int lin = tid + i * 512;
            const int r   = lin >> 3;
            const int cc  = lin & 7;
            const uint32_t off = (uint32_t)(r * (SPH * 2) + cc * 16);
            cpa16(a_st + off, Abase + (size_t)r * K + kof + cc * 8);
            cpa16(b_st + off, Bbase + (size_t)r * K + kof + cc * 8);
        }
    };

    #pragma unroll
    for (int p = 0; p < GSTAGES - 1; p++) {
        load_stage(p);
        asm volatile("cp.async.commit_group;" ::: "memory");
    }

    for (int c = 0; c < NC; c++) {
        asm volatile("cp.async.wait_group %0;" :: "n"(GSTAGES - 2) : "memory");
        __syncthreads();

        if (c + GSTAGES - 1 < NC) load_stage(c + GSTAGES - 1);
        asm volatile("cp.async.commit_group;" ::: "memory");

        const uint32_t stage_base = smem_base + (c % GSTAGES) * STAGE_H * 2;
        const uint32_t aAddr = stage_base + aOff;
        const uint32_t bAddr = stage_base + TILE_H * 2 + bOff;

        #pragma unroll
        for (int ks = 0; ks < 4; ks++) {
            uint32_t af[2][4], bf[4][2];
            ldsm4(af[0][0], af[0][1], af[0][2], af[0][3], aAddr + ks * 32);
            ldsm4(af[1][0], af[1][1], af[1][2], af[1][3],
                  aAddr + 16 * SPH * 2 + ks * 32);
            ldsm4(bf[0][0], bf[0][1], bf[1][0], bf[1][1], bAddr + ks * 32);
            ldsm4(bf[2][0], bf[2][1], bf[3][0], bf[3][1],
                  bAddr + 16 * SPH * 2 + ks * 32);
            #pragma unroll
            for (int im = 0; im < 2; im++)
                #pragma unroll
                for (int jn = 0; jn < 4; jn++)
                    mma_f16(acc[im][jn][0], acc[im][jn][1],
                            acc[im][jn][2], acc[im][jn][3],
                            af[im][0], af[im][1], af[im][2], af[im][3],
                            bf[jn][0], bf[jn][1]);
        }
    }

    // ---- epilogue ----------------------------------------------------------
    const bool vpart = (EPI == EPI_QKV) && (ncol0 >= 2 * DMODEL);
    const bool qpart = (EPI == EPI_QKV) && (ncol0 < DMODEL);
    #pragma unroll
    for (int im = 0; im < 2; im++) {
        const int r0 = mrow0 + warpM * 32 + im * 16 + gi;
        #pragma unroll
        for (int hf = 0; hf < 2; hf++) {
            const size_t row = (size_t)(r0 + hf * 8);
            #pragma unroll
            for (int jn = 0; jn < 4; jn++) {
                const int col = ncol0 + warpN * 32 + jn * 8 + tig * 2;
                float ox = acc[im][jn][hf * 2 + 0];
                float oy = acc[im][jn][hf * 2 + 1];
                float2 bv = *(const float2*)(bias + col);
                ox += bv.x; oy += bv.y;
                if (EPI == EPI_RES) {
                    float2 rv = *(const float2*)(res + row * N + col);
                    float2 o2 = {ox + rv.x, oy + rv.y};
                    *(float2*)((float*)Cv + row * N + col) = o2;
                } else if (EPI == EPI_GELU) {
                    __half2 hv = __floats2half2_rn(gelu_exact(ox), gelu_exact(oy));
                    *(__half2*)((__half*)Cv + row * N + col) = hv;
                } else {  // EPI_QKV
                    if (vpart) {
                        const int vcol = col - 2 * DMODEL;
                        const int hh = vcol >> 6, d = vcol & 63;
                        const int bb = (int)(row >> 11), tok = (int)(row & 2047);
                        __half* vp = vT +
                            ((size_t)((bb * NHEADS + hh) * HDIM + d)) * SEQ + tok;
                        vp[0]   = __float2half(ox);
                        vp[SEQ] = __float2half(oy);
                    } else {
                        if (qpart) { ox *= 0.125f; oy *= 0.125f; }  // exact 2^-3
                        __half2 hv = __floats2half2_rn(ox, oy);
                        *(__half2*)((__half*)Cv + row * N + col) = hv;
                    }
                }
            }
        }
    }
}

// --------------- GEMM B: 256x128 tile, 1 CTA/SM (proj / mlp) ----------------
#define A_TILE_H (256 * SPH)
#define B_TILE_H (128 * SPH)
#define STAGE2_H (A_TILE_H + B_TILE_H)
#define GSMEM2_DYN (GSTAGES * STAGE2_H * 2)   // 165888 B -> 1 CTA/SM

template <int EPI>
__global__ void __launch_bounds__(512, 1) hgemm256_kernel(
    const __half* __restrict__ A, const __half* __restrict__ Bt,
    const float* __restrict__ bias, const float* __restrict__ res,
    void* __restrict__ Cv, int M, int N, int K)
{
    extern __shared__ __half smh[];

    const int tid   = threadIdx.x;
    const int wid   = tid >> 5;
    const int lane  = tid & 31;
    const int gi    = lane >> 2;
    const int tig   = lane & 3;
    const int warpM = wid >> 2;
    const int warpN = wid & 3;

    const int mrow0 = blockIdx.y * 256;
    const int ncol0 = blockIdx.x * 128;

    const __half* Abase = A  + (size_t)mrow0 * K;
    const __half* Bbase = Bt + (size_t)ncol0 * K;

    const uint32_t smem_base = smem_u32(smh);

    const uint32_t aOff = (uint32_t)(
        (warpM * 64 + (lane & 7) + (((lane >> 3) & 1) << 3)) * SPH
        + ((lane >> 4) << 3)) * 2;
    const uint32_t bOff = (uint32_t)(
        (warpN * 32 + (lane & 7) + ((lane >> 4) << 3)) * SPH
        + (((lane >> 3) & 1) << 3)) * 2;

    float acc[4][4][4];
    #pragma unroll
    for (int i = 0; i < 4; i++)
        #pragma unroll
        for (int j = 0; j < 4; j++)
            #pragma unroll
            for (int q = 0; q < 4; q++) acc[i][j][q] = 0.f;

    const int NC = K / BKH;

    auto load_stage = [&](int c) {
        const int s = c % GSTAGES;
        const uint32_t a_st = smem_base + s * STAGE2_H * 2;
        const uint32_t b_st = a_st + A_TILE_H * 2;
        const int kof = c * BKH;
        #pragma unroll
        for (int i = 0; i < 6; i++) {
            const int lin = tid + i * 512;
            if (lin < 2048) {
                const int r  = lin >> 3;
                const int cc = lin & 7;
                const uint32_t off = (uint32_t)(r * (SPH * 2) + cc * 16);
                cpa16(a_st + off, Abase + (size_t)r * K + kof + cc * 8);
            } else {
                const int j  = lin - 2048;
                const int r  = j >> 3;
                const int cc = j & 7;
                const uint32_t off = (uint32_t)(r * (SPH * 2) + cc * 16);
                cpa16(b_st + off, Bbase + (size_t)r * K + kof + cc * 8);
            }
        }
    };

    #pragma unroll
    for (int p = 0; p < GSTAGES - 1; p++) {
        load_stage(p);
        asm volatile("cp.async.commit_group;" ::: "memory");
    }

    for (int c = 0; c < NC; c++) {
        asm volatile("cp.async.wait_group %0;" :: "n"(GSTAGES - 2) : "memory");
        __syncthreads();

        if (c + GSTAGES - 1 < NC) load_stage(c + GSTAGES - 1);
        asm volatile("cp.async.commit_group;" ::: "memory");

        const uint32_t stage_base = smem_base + (c % GSTAGES) * STAGE2_H * 2;
        const uint32_t aAddr = stage_base + aOff;
        const uint32_t bAddr = stage_base + A_TILE_H * 2 + bOff;

        #pragma unroll
        for (int ks = 0; ks < 4; ks++) {
            uint32_t af[4][4], bf[4][2];
            #pragma unroll
            for (int im = 0; im < 4; im++)
                ldsm4(af[im][0], af[im][1], af[im][2], af[im][3],
                      aAddr + im * (16 * SPH * 2) + ks * 32);
            ldsm4(bf[0][0], bf[0][1], bf[1][0], bf[1][1], bAddr + ks * 32);
            ldsm4(bf[2][0], bf[2][1], bf[3][0], bf[3][1],
                  bAddr + 16 * SPH * 2 + ks * 32);
            #pragma unroll
            for (int im = 0; im < 4; im++)
                #pragma unroll
                for (int jn = 0; jn < 4; jn++)
                    mma_f16(acc[im][jn][0], acc[im][jn][1],
                            acc[im][jn][2], acc[im][jn][3],
                            af[im][0], af[im][1], af[im][2], af[im][3],
                            bf[jn][0], bf[jn][1]);
        }
    }

    // ---- epilogue (EPI_RES only) -------------------------------------------
    #pragma unroll
    for (int im = 0; im < 4; im++) {
        const int r0 = mrow0 + warpM * 64 + im * 16 + gi;
        #pragma unroll
        for (int hf = 0; hf < 2; hf++) {
            const size_t row = (size_t)(r0 + hf * 8);
            #pragma unroll
            for (int jn = 0; jn < 4; jn++) {
                const int col = ncol0 + warpN * 32 + jn * 8 + tig * 2;
                float ox = acc[im][jn][hf * 2 + 0];
                float oy = acc[im][jn][hf * 2 + 1];
                float2 bv = *(const float2*)(bias + col);
                ox += bv.x; oy += bv.y;
                float2 rv = *(const float2*)(res + row * N + col);
                float2 o2 = {ox + rv.x, oy + rv.y};
                *(float2*)((float*)Cv + row * N + col) = o2;
            }
        }
    }
}

// ------------------------- Flash attention (fp16 MMA) -----------------------
// 128 q-rows per CTA (8 warps x 16 rows), 64-key tiles, double-buffered K/V.
// Q pre-scaled by 1/8 at the QKV epilogue.
#define KVH    (64 * SPH)
#define P_OFF  (4 * KVH)
#define ATTN_SMEM_B ((4 * KVH + 128 * SPH) * 2)   // 55296 B

__global__ void __launch_bounds__(256, 2) attn_kernel(
    const __half* __restrict__ qkv, const __half* __restrict__ vT,
    __half* __restrict__ out)
{
    extern __shared__ __half smh[];
    const uint32_t smem_base = smem_u32(smh);

    const int qt  = (int)gridDim.x - 1 - (int)blockIdx.x;  // heavy tiles first
    const int b   = blockIdx.y >> 4;
    const int h   = blockIdx.y & 15;
    const int tid = threadIdx.x;
    const int wid = tid >> 5;
    const int lane = tid & 31;
    const int gi  = lane >> 2;
    const int tig = lane & 3;

    const int q0 = qt * 128;
    const int qrow_w = q0 + wid * 16;
    const int nkt = qt * 2 + 2;

    const uint32_t nkOff = (uint32_t)(
        ((lane & 7) + ((lane >> 4) << 3)) * SPH
        + (((lane >> 3) & 1) << 3)) * 2;
    const uint32_t pOff = (uint32_t)(
        (wid * 16 + (lane & 7) + (((lane >> 3) & 1) << 3)) * SPH
        + ((lane >> 4) << 3)) * 2;

    auto load_tile = [&](int kt) {
        const int st = kt & 1;
        const __half* Kg = qkv + ((size_t)(b * SEQ + kt * 64)) * 3072
                           + DMODEL + h * HDIM;
        const __half* Vg = vT + ((size_t)((b * NHEADS + h) * HDIM)) * SEQ + kt * 64;
        const uint32_t Kd = smem_base + st * (KVH * 2);
        const uint32_t Vd = smem_base + (2 + st) * (KVH * 2);
        #pragma unroll
        for (int i = 0; i < 4; i++) {
            const int idx = tid + i * 256;
            if (idx < 512) {
                const int r = idx >> 3, cc = idx & 7;
                cpa16(Kd + r * (SPH * 2) + cc * 16, Kg + (size_t)r * 3072 + cc * 8);
            } else {
                const int j = idx - 512;
                const int r = j >> 3, cc = j & 7;
                cpa16(Vd + r * (SPH * 2) + cc * 16, Vg + (size_t)r * SEQ + cc * 8);
            }
        }
    };

    {
        const __half* Qg = qkv + ((size_t)(b * SEQ + q0)) * 3072 + h * HDIM;
        const uint32_t Pd = smem_base + P_OFF * 2;
        #pragma unroll
        for (int i = 0; i < 4; i++) {
            const int idx = tid + i * 256;
            const int r = idx >> 3, cc = idx & 7;
            cpa16(Pd + r * (SPH * 2) + cc * 16, Qg + (size_t)r * 3072 + cc * 8);
        }
        asm volatile("cp.async.commit_group;" ::: "memory");
        load_tile(0);
        asm volatile("cp.async.commit_group;" ::: "memory");
        asm volatile("cp.async.wait_group 0;" ::: "memory");
        __syncthreads();
    }

    uint32_t qf[4][4];
    {
        const uint32_t qAddr = smem_base + P_OFF * 2 + pOff;
        #pragma unroll
        for (int ks = 0; ks < 4; ks++)
            ldsm4(qf[ks][0], qf[ks][1], qf[ks][2], qf[ks][3], qAddr + ks * 32);
    }

    float m[2] = {-1e30f, -1e30f};
    float l[2] = {0.f, 0.f};
    float o[8][4];
    #pragma unroll
    for (int jn = 0; jn < 8; jn++)
        #pragma unroll
        for (int q = 0; q < 4; q++) o[jn][q] = 0.f;

    for (int kt = 0; kt < nkt; kt++) {
        if (kt > 0) {
            asm volatile("cp.async.wait_group 0;" ::: "memory");
            __syncthreads();
        }
        if (kt + 1 < nkt) {
            load_tile(kt + 1);
            asm volatile("cp.async.commit_group;" ::: "memory");
        }

        const int st = kt & 1;
        const uint32_t kAddr = smem_base + st * (KVH * 2) + nkOff;
        const uint32_t vAddr = smem_base + (2 + st) * (KVH * 2) + nkOff;

        // ---- S = (Q/8) @ K^T ----
        float s[8][4];
        #pragma unroll
        for (int jn = 0; jn < 8; jn++)
            #pragma unroll
            for (int q = 0; q < 4; q++) s[jn][q] = 0.f;

        #pragma unroll
        for (int ks = 0; ks < 4; ks++) {
            uint32_t bf[8][2];
            #pragma unroll
            for (int jnp = 0; jnp < 4; jnp++)
                ldsm4(bf[2 * jnp][0], bf[2 * jnp][1],
                      bf[2 * jnp + 1][0], bf[2 * jnp + 1][1],
                      kAddr + jnp * (16 * SPH * 2) + ks * 32);
            #pragma unroll
            for (int jn = 0; jn < 8; jn++)
                mma_f16(s[jn][0], s[jn][1], s[jn][2], s[jn][3],
                        qf[ks][0], qf[ks][1], qf[ks][2], qf[ks][3],
                        bf[jn][0], bf[jn][1]);
        }

        if (kt * 64 + 63 > qrow_w) {
            #pragma unroll
            for (int jn = 0; jn < 8; jn++) {
                const int kc = kt * 64 + jn * 8 + tig * 2;
                const int r0 = qrow_w + gi;
                const int r1 = r0 + 8;
                if (kc     > r0) s[jn][0] = -1e30f;
                if (kc + 1 > r0) s[jn][1] = -1e30f;
                if (kc     > r1) s[jn][2] = -1e30f;
                if (kc + 1 > r1) s[jn][3] = -1e30f;
            }
        }

        #pragma unroll
        for (int rr = 0; rr < 2; rr++) {
            const int i0 = rr * 2, i1 = rr * 2 + 1;
            float mx = -1e30f;
            #pragma unroll
            for (int jn = 0; jn < 8; jn++)
                mx = fmaxf(mx, fmaxf(s[jn][i0], s[jn][i1]));
            mx = fmaxf(mx, __shfl_xor_sync(0xffffffffu, mx, 1));
            mx = fmaxf(mx, __shfl_xor_sync(0xffffffffu, mx, 2));
            const float mn = fmaxf(m[rr], mx);
            const float al = __expf(m[rr] - mn);
            float rs = 0.f;
            #pragma unroll
            for (int jn = 0; jn < 8; jn++) {
                const float e0 = __expf(s[jn][i0] - mn);
                const float e1 = __expf(s[jn][i1] - mn);
                s[jn][i0] = e0; s[jn][i1] = e1;
                rs += e0 + e1;
            }
            rs += __shfl_xor_sync(0xffffffffu, rs, 1);
            rs += __shfl_xor_sync(0xffffffffu, rs, 2);
            l[rr] = l[rr] * al + rs;
            m[rr] = mn;
            #pragma unroll
            for (int jn = 0; jn < 8; jn++) { o[jn][i0] *= al; o[jn][i1] *= al; }
        }

        {
            uint32_t* Pst = (uint32_t*)(smh + P_OFF) + (wid * 16 + gi) * SPW;
            #pragma unroll
            for (int jn = 0; jn < 8; jn++) {
                __half2 p0 = __floats2half2_rn(s[jn][0], s[jn][1]);
                __half2 p1 = __floats2half2_rn(s[jn][2], s[jn][3]);
                Pst[jn * 4 + tig]           = *(uint32_t*)&p0;
                Pst[8 * SPW + jn * 4 + tig] = *(uint32_t*)&p1;
            }
        }
        __syncwarp();

        const uint32_t pAddr = smem_base + P_OFF * 2 + pOff;
        #pragma unroll
        for (int ks = 0; ks < 4; ks++) {
            uint32_t a0, a1, a2, a3;
            ldsm4(a0, a1, a2, a3, pAddr + ks * 32);
            uint32_t vf[8][2];
            #pragma unroll
            for (int jnp = 0; jnp < 4; jnp++)
                ldsm4(vf[2 * jnp][0], vf[2 * jnp][1],
                      vf[2 * jnp + 1][0], vf[2 * jnp + 1][1],
                      vAddr + jnp * (16 * SPH * 2) + ks * 32);
            #pragma unroll
            for (int jn = 0; jn < 8; jn++)
                mma_f16(o[jn][0], o[jn][1], o[jn][2], o[jn][3],
                        a0, a1, a2, a3, vf[jn][0], vf[jn][1]);
        }
        __syncwarp();
    }

    const float inv0 = 1.0f / l[0];
    const float inv1 = 1.0f / l[1];
    __half* O0 = out + ((size_t)(b * SEQ) + qrow_w + gi)     * DMODEL + h * HDIM;
    __half* O1 = out + ((size_t)(b * SEQ) + qrow_w + gi + 8) * DMODEL + h * HDIM;
    #pragma unroll
    for (int jn = 0; jn < 8; jn++) {
        __half2 v0 = __floats2half2_rn(o[jn][0] * inv0, o[jn][1] * inv0);
        __half2 v1 = __floats2half2_rn(o[jn][2] * inv1, o[jn][3] * inv1);
        *(__half2*)(O0 + jn * 8 + tig * 2) = v0;
        *(__half2*)(O1 + jn * 8 + tig * 2) = v1;
    }
}

// ------------------------------- launcher -----------------------------------
extern "C" void kernel_launch(void* const* d_in, const int* in_sizes, int n_in,
                              void* d_out, int out_size)
{
    const float* hidden = (const float*)d_in[0];
    const float* w_qkv  = (const float*)d_in[1];
    const float* b_qkv  = (const float*)d_in[2];
    const float* g1     = (const float*)d_in[3];
    const float* be1    = (const float*)d_in[4];
    const float* w_proj = (const float*)d_in[5];
    const float* b_proj = (const float*)d_in[6];
    const float* g2     = (const float*)d_in[7];
    const float* be2    = (const float*)d_in[8];
    const float* w_fc   = (const float*)d_in[9];
    const float* b_fc   = (const float*)d_in[10];
    const float* w_mlp  = (const float*)d_in[11];
    const float* b_mlp  = (const float*)d_in[12];
    float* out = (float*)d_out;

    __half *x, *qkv, *vT, *attn, *y, *fc, *wT;
    float  *h2;
    cudaGetSymbolAddress((void**)&x,    g_x);
    cudaGetSymbolAddress((void**)&qkv,  g_qkv);
    cudaGetSymbolAddress((void**)&vT,   g_vT);
    cudaGetSymbolAddress((void**)&attn, g_attn);
    cudaGetSymbolAddress((void**)&h2,   g_h2);
    cudaGetSymbolAddress((void**)&y,    g_y);
    cudaGetSymbolAddress((void**)&fc,   g_fc);
    cudaGetSymbolAddress((void**)&wT,   g_wT);

    __half* wT_qkv  = wT + WT_QKV_OFF;
    __half* wT_proj = wT + WT_PROJ_OFF;
    __half* wT_fc   = wT + WT_FC_OFF;
    __half* wT_mlp  = wT + WT_MLP_OFF;

    cudaFuncSetAttribute(attn_kernel,
                         cudaFuncAttributeMaxDynamicSharedMemorySize, ATTN_SMEM_B);
    cudaFuncSetAttribute(hgemm_kernel<EPI_QKV>,
                         cudaFuncAttributeMaxDynamicSharedMemorySize, GSMEM_DYN);
    cudaFuncSetAttribute(hgemm_kernel<EPI_GELU>,
                         cudaFuncAttributeMaxDynamicSharedMemorySize, GSMEM_DYN);
    cudaFuncSetAttribute(hgemm256_kernel<EPI_RES>,
                         cudaFuncAttributeMaxDynamicSharedMemorySize, GSMEM2_DYN);

    // 1. prep: LN1 + all 4 weight transposes in one launch
    prep_kernel<<<ROWS + 12288, 256>>>(hidden, g1, be1, x,
                                       w_qkv, w_proj, w_fc, w_mlp, wT);
    // 2. QKV (Q pre-scaled 1/8; K -> qkv half; V -> vT transposed)
    hgemm_kernel<EPI_QKV><<<dim3(3 * DMODEL / 128, ROWS / 128), 512, GSMEM_DYN>>>(
        x, wT_qkv, b_qkv, nullptr, qkv, vT, ROWS, 3 * DMODEL, DMODEL);
    // 3. attention -> half
    attn_kernel<<<dim3(SEQ / 128, BATCH * NHEADS), 256, ATTN_SMEM_B>>>(qkv, vT, attn);
    // 4. h2 = attn @ w_proj + b_proj + hidden  (f32)  [256-row tiles]
    hgemm256_kernel<EPI_RES><<<dim3(DMODEL / 128, ROWS / 256), 512, GSMEM2_DYN>>>(
        attn, wT_proj, b_proj, hidden, h2, ROWS, DMODEL, DMODEL);
    // 5. LN2 -> half
    ln_kernel<<<ROWS, 256>>>(h2, g2, be2, y);
    // 6. fc = gelu(y @ w_fc + b_fc) -> half
    hgemm_kernel<EPI_GELU><<<dim3(INNER / 128, ROWS / 128), 512, GSMEM_DYN>>>(
        y, wT_fc, b_fc, nullptr, fc, nullptr, ROWS, INNER, DMODEL);
    // 7. out = fc @ w_mlp + b_mlp + h2  (f32)  [256-row tiles]
    hgemm256_kernel<EPI_RES><<<dim3(DMODEL / 128, ROWS / 256), 512, GSMEM2_DYN>>>(
        fc, wT_mlp, b_mlp, h2, out, ROWS, DMODEL, INNER);
}

// round 17
// speedup vs baseline: 1.2269x; 1.0199x over previous
#include <cuda_runtime.h>
#include <cuda_fp16.h>
#include <math.h>
#include <stdint.h>

// ---------------------------------------------------------------------------
// GPT-2 block, fp16 mma.sync + ldmatrix. R17: R16 + attention keeps P entirely
// in registers (S C-fragments repacked directly as P@V A-fragments; no smem
// round trip, no syncwarps).
// B=2, S=2048, D=1024, H=16, dh=64, INNER=4096
// ---------------------------------------------------------------------------

#define BATCH   2
#define SEQ     2048
#define DMODEL  1024
#define NHEADS  16
#define HDIM    64
#define INNER   4096
#define ROWS    (BATCH * SEQ)
#define EPS     1e-5f

// ------------------------- scratch (static device mem) ---------------------
__device__ __half g_x   [ROWS * DMODEL];
__device__ __half g_qkv [ROWS * 3 * DMODEL];
__device__ __half g_vT  [BATCH * NHEADS * HDIM * SEQ];
__device__ __half g_attn[ROWS * DMODEL];
__device__ float  g_h2  [ROWS * DMODEL];
__device__ __half g_y   [ROWS * DMODEL];
__device__ __half g_fc  [ROWS * INNER];
__device__ __half g_wT  [12 * 1024 * 1024];
#define WT_QKV_OFF  0
#define WT_PROJ_OFF (3072 * 1024)
#define WT_FC_OFF   (WT_PROJ_OFF + 1024 * 1024)
#define WT_MLP_OFF  (WT_FC_OFF + 4096 * 1024)

// ------------------------------ small helpers -------------------------------
__device__ __forceinline__ float gelu_exact(float x) {
    return 0.5f * x * (1.0f + erff(x * 0.70710678118654752f));
}

__device__ __forceinline__ uint32_t smem_u32(const void* p) {
    uint32_t a;
    asm("{ .reg .u64 t; cvta.to.shared.u64 t, %1; cvt.u32.u64 %0, t; }"
        : "=r"(a) : "l"(p));
    return a;
}

__device__ __forceinline__ void cpa16(uint32_t dst, const void* src) {
    asm volatile("cp.async.cg.shared.global [%0], [%1], 16;" :: "r"(dst), "l"(src));
}

__device__ __forceinline__ void mma_f16(
    float& c0, float& c1, float& c2, float& c3,
    uint32_t a0, uint32_t a1, uint32_t a2, uint32_t a3,
    uint32_t b0, uint32_t b1)
{
    asm volatile(
        "mma.sync.aligned.m16n8k16.row.col.f32.f16.f16.f32 "
        "{%0,%1,%2,%3}, {%4,%5,%6,%7}, {%8,%9}, {%0,%1,%2,%3};"
        : "+f"(c0), "+f"(c1), "+f"(c2), "+f"(c3)
        : "r"(a0), "r"(a1), "r"(a2), "r"(a3), "r"(b0), "r"(b1));
}

__device__ __forceinline__ void ldsm4(
    uint32_t& r0, uint32_t& r1, uint32_t& r2, uint32_t& r3, uint32_t addr)
{
    asm volatile(
        "ldmatrix.sync.aligned.m8n8.x4.shared.b16 {%0,%1,%2,%3}, [%4];"
        : "=r"(r0), "=r"(r1), "=r"(r2), "=r"(r3) : "r"(addr));
}

// --------------------------- LayerNorm row body -----------------------------
__device__ __forceinline__ void ln_row(
    const float* __restrict__ in, const float* __restrict__ gamma,
    const float* __restrict__ beta, __half* __restrict__ out, int row)
{
    __shared__ float red[16];
    const int tid = threadIdx.x;
    const float* x = in + (size_t)row * DMODEL;

    float4 v = *(const float4*)(x + tid * 4);
    float s = v.x + v.y + v.z + v.w;
    float q = v.x * v.x + v.y * v.y + v.z * v.z + v.w * v.w;
    #pragma unroll
    for (int off = 16; off; off >>= 1) {
        s += __shfl_xor_sync(0xffffffffu, s, off);
        q += __shfl_xor_sync(0xffffffffu, q, off);
    }
    const int w = tid >> 5;
    if ((tid & 31) == 0) { red[w] = s; red[8 + w] = q; }
    __syncthreads();
    float st = 0.f, qt = 0.f;
    #pragma unroll
    for (int i = 0; i < 8; i++) { st += red[i]; qt += red[8 + i]; }

    const float mu  = st * (1.0f / DMODEL);
    const float var = qt * (1.0f / DMODEL) - mu * mu;
    const float inv = rsqrtf(var + EPS);

    float4 g = *(const float4*)(gamma + tid * 4);
    float4 b = *(const float4*)(beta  + tid * 4);
    __half2 p0 = __floats2half2_rn((v.x - mu) * inv * g.x + b.x,
                                   (v.y - mu) * inv * g.y + b.y);
    __half2 p1 = __floats2half2_rn((v.z - mu) * inv * g.z + b.z,
                                   (v.w - mu) * inv * g.w + b.w);
    uint2 pk;
    pk.x = *(uint32_t*)&p0;
    pk.y = *(uint32_t*)&p1;
    *(uint2*)(out + (size_t)row * DMODEL + tid * 4) = pk;
}

__global__ void __launch_bounds__(256) ln_kernel(
    const float* __restrict__ in, const float* __restrict__ gamma,
    const float* __restrict__ beta, __half* __restrict__ out)
{
    ln_row(in, gamma, beta, out, blockIdx.x);
}

// ---------------- fused prep: LN1 + 4 weight transposes ---------------------
__global__ void __launch_bounds__(256) prep_kernel(
    const float* __restrict__ hidden, const float* __restrict__ g1,
    const float* __restrict__ be1, __half* __restrict__ x,
    const float* __restrict__ w_qkv, const float* __restrict__ w_proj,
    const float* __restrict__ w_fc,  const float* __restrict__ w_mlp,
    __half* __restrict__ wT)
{
    const int bid = blockIdx.x;
    if (bid < ROWS) {
        ln_row(hidden, g1, be1, x, bid);
        return;
    }
    int t = bid - ROWS;
    const float* in;
    __half* outp;
    int K, N, bx, by;
    if (t < 3072)      { in = w_qkv;  outp = (__half*)wT + WT_QKV_OFF;
                         K = 1024; N = 3072; bx = t % 96;  by = t / 96; }
    else if (t < 4096) { t -= 3072; in = w_proj; outp = (__half*)wT + WT_PROJ_OFF;
                         K = 1024; N = 1024; bx = t % 32;  by = t / 32; }
    else if (t < 8192) { t -= 4096; in = w_fc;   outp = (__half*)wT + WT_FC_OFF;
                         K = 1024; N = 4096; bx = t % 128; by = t / 128; }
    else               { t -= 8192; in = w_mlp;  outp = (__half*)wT + WT_MLP_OFF;
                         K = 4096; N = 1024; bx = t % 32;  by = t / 32; }

    __shared__ float t2[32][33];
    const int n0 = bx * 32, k0 = by * 32;
    const int tid = threadIdx.x;
    const int lr = tid >> 3;
    const int lc = tid & 7;

    float4 v4 = *(const float4*)(in + (size_t)(k0 + lr) * N + n0 + lc * 4);
    t2[lc * 4 + 0][lr] = v4.x;
    t2[lc * 4 + 1][lr] = v4.y;
    t2[lc * 4 + 2][lr] = v4.z;
    t2[lc * 4 + 3][lr] = v4.w;
    __syncthreads();

    __half2 h0 = __floats2half2_rn(t2[lr][lc * 4 + 0], t2[lr][lc * 4 + 1]);
    __half2 h1 = __floats2half2_rn(t2[lr][lc * 4 + 2], t2[lr][lc * 4 + 3]);
    uint2 pk2;
    pk2.x = *(uint32_t*)&h0;
    pk2.y = *(uint32_t*)&h1;
    *(uint2*)(outp + (size_t)(n0 + lr) * K + k0 + lc * 4) = pk2;
}

// ------------------------------ common defs ---------------------------------
#define EPI_QKV   0
#define EPI_RES   1
#define EPI_GELU  2

#define BKH      64
#define SPH      72
#define SPW      (SPH / 2)

// --------------- GEMM A: 128x128 tile, 2 CTA/SM (qkv / fc) ------------------
#define TILE_H   (128 * SPH)
#define STAGE_H  (2 * TILE_H)
#define GSTAGES  3
#define GSMEM_DYN (GSTAGES * STAGE_H * 2)   // 110592 B -> 2 CTAs/SM

template <int EPI>
__global__ void __launch_bounds__(512, 2) hgemm_kernel(
    const __half* __restrict__ A, const __half* __restrict__ Bt,
    const float* __restrict__ bias, const float* __restrict__ res,
    void* __restrict__ Cv, __half* __restrict__ vT, int M, int N, int K)
{
    extern __shared__ __half smh[];

    const int tid   = threadIdx.x;
    const int wid   = tid >> 5;
    const int lane  = tid & 31;
    const int gi    = lane >> 2;
    const int tig   = lane & 3;
    const int warpM = wid >> 2;
    const int warpN = wid & 3;

    const int mrow0 = blockIdx.y * 128;
    const int ncol0 = blockIdx.x * 128;

    const __half* Abase = A  + (size_t)mrow0 * K;
    const __half* Bbase = Bt + (size_t)ncol0 * K;

    const uint32_t smem_base = smem_u32(smh);

    const uint32_t aOff = (uint32_t)(
        (warpM * 32 + (lane & 7) + (((lane >> 3) & 1) << 3)) * SPH
        + ((lane >> 4) << 3)) * 2;
    const uint32_t bOff = (uint32_t)(
        (warpN * 32 + (lane & 7) + ((lane >> 4) << 3)) * SPH
        + (((lane >> 3) & 1) << 3)) * 2;

    float acc[2][4][4];
    #pragma unroll
    for (int i = 0; i < 2; i++)
        #pragma unroll
        for (int j = 0; j < 4; j++)
            #pragma unroll
            for (int q = 0; q < 4; q++) acc[i][j][q] = 0.f;

    const int NC = K / BKH;

    auto load_stage = [&](int c) {
        const int s = c % GSTAGES;
        const uint32_t a_st = smem_base + s * STAGE_H * 2;
        const uint32_t b_st = a_st + TILE_H * 2;
        const int kof = c * BKH;
        #pragma unroll
        for (int i = 0; i < 2; i++) {
            const int lin = tid + i * 512;
            const int r   = lin >> 3;
            const int cc  = lin & 7;
            const uint32_t off = (uint32_t)(r * (SPH * 2) + cc * 16);
            cpa16(a_st + off, Abase + (size_t)r * K + kof + cc * 8);
            cpa16(b_st + off, Bbase + (size_t)r * K + kof + cc * 8);
        }
    };

    #pragma unroll
    for (int p = 0; p < GSTAGES - 1; p++) {
        load_stage(p);
        asm volatile("cp.async.commit_group;" ::: "memory");
    }

    for (int c = 0; c < NC; c++) {
        asm volatile("cp.async.wait_group %0;" :: "n"(GSTAGES - 2) : "memory");
        __syncthreads();

        if (c + GSTAGES - 1 < NC) load_stage(c + GSTAGES - 1);
        asm volatile("cp.async.commit_group;" ::: "memory");

        const uint32_t stage_base = smem_base + (c % GSTAGES) * STAGE_H * 2;
        const uint32_t aAddr = stage_base + aOff;
        const uint32_t bAddr = stage_base + TILE_H * 2 + bOff;

        #pragma unroll
        for (int ks = 0; ks < 4; ks++) {
            uint32_t af[2][4], bf[4][2];
            ldsm4(af[0][0], af[0][1], af[0][2], af[0][3], aAddr + ks * 32);
            ldsm4(af[1][0], af[1][1], af[1][2], af[1][3],
                  aAddr + 16 * SPH * 2 + ks * 32);
            ldsm4(bf[0][0], bf[0][1], bf[1][0], bf[1][1], bAddr + ks * 32);
            ldsm4(bf[2][0], bf[2][1], bf[3][0], bf[3][1],
                  bAddr + 16 * SPH * 2 + ks * 32);
            #pragma unroll
            for (int im = 0; im < 2; im++)
                #pragma unroll
                for (int jn = 0; jn < 4; jn++)
                    mma_f16(acc[im][jn][0], acc[im][jn][1],
                            acc[im][jn][2], acc[im][jn][3],
                            af[im][0], af[im][1], af[im][2], af[im][3],
                            bf[jn][0], bf[jn][1]);
        }
    }

    // ---- epilogue ----------------------------------------------------------
    const bool vpart = (EPI == EPI_QKV) && (ncol0 >= 2 * DMODEL);
    const bool qpart = (EPI == EPI_QKV) && (ncol0 < DMODEL);
    #pragma unroll
    for (int im = 0; im < 2; im++) {
        const int r0 = mrow0 + warpM * 32 + im * 16 + gi;
        #pragma unroll
        for (int hf = 0; hf < 2; hf++) {
            const size_t row = (size_t)(r0 + hf * 8);
            #pragma unroll
            for (int jn = 0; jn < 4; jn++) {
                const int col = ncol0 + warpN * 32 + jn * 8 + tig * 2;
                float ox = acc[im][jn][hf * 2 + 0];
                float oy = acc[im][jn][hf * 2 + 1];
                float2 bv = *(const float2*)(bias + col);
                ox += bv.x; oy += bv.y;
                if (EPI == EPI_RES) {
                    float2 rv = *(const float2*)(res + row * N + col);
                    float2 o2 = {ox + rv.x, oy + rv.y};
                    *(float2*)((float*)Cv + row * N + col) = o2;
                } else if (EPI == EPI_GELU) {
                    __half2 hv = __floats2half2_rn(gelu_exact(ox), gelu_exact(oy));
                    *(__half2*)((__half*)Cv + row * N + col) = hv;
                } else {  // EPI_QKV
                    if (vpart) {
                        const int vcol = col - 2 * DMODEL;
                        const int hh = vcol >> 6, d = vcol & 63;
                        const int bb = (int)(row >> 11), tok = (int)(row & 2047);
                        __half* vp = vT +
                            ((size_t)((bb * NHEADS + hh) * HDIM + d)) * SEQ + tok;
                        vp[0]   = __float2half(ox);
                        vp[SEQ] = __float2half(oy);
                    } else {
                        if (qpart) { ox *= 0.125f; oy *= 0.125f; }  // exact 2^-3
                        __half2 hv = __floats2half2_rn(ox, oy);
                        *(__half2*)((__half*)Cv + row * N + col) = hv;
                    }
                }
            }
        }
    }
}

// --------------- GEMM B: 256x128 tile, 1 CTA/SM (proj / mlp) ----------------
#define A_TILE_H (256 * SPH)
#define B_TILE_H (128 * SPH)
#define STAGE2_H (A_TILE_H + B_TILE_H)
#define GSMEM2_DYN (GSTAGES * STAGE2_H * 2)   // 165888 B -> 1 CTA/SM

template <int EPI>
__global__ void __launch_bounds__(512, 1) hgemm256_kernel(
    const __half* __restrict__ A, const __half* __restrict__ Bt,
    const float* __restrict__ bias, const float* __restrict__ res,
    void* __restrict__ Cv, int M, int N, int K)
{
    extern __shared__ __half smh[];

    const int tid   = threadIdx.x;
    const int wid   = tid >> 5;
    const int lane  = tid & 31;
    const int gi    = lane >> 2;
    const int tig   = lane & 3;
    const int warpM = wid >> 2;
    const int warpN = wid & 3;

    const int mrow0 = blockIdx.y * 256;
    const int ncol0 = blockIdx.x * 128;

    const __half* Abase = A  + (size_t)mrow0 * K;
    const __half* Bbase = Bt + (size_t)ncol0 * K;

    const uint32_t smem_base = smem_u32(smh);

    const uint32_t aOff = (uint32_t)(
        (warpM * 64 + (lane & 7) + (((lane >> 3) & 1) << 3)) * SPH
        + ((lane >> 4) << 3)) * 2;
    const uint32_t bOff = (uint32_t)(
        (warpN * 32 + (lane & 7) + ((lane >> 4) << 3)) * SPH
        + (((lane >> 3) & 1) << 3)) * 2;

    float acc[4][4][4];
    #pragma unroll
    for (int i = 0; i < 4; i++)
        #pragma unroll
        for (int j = 0; j < 4; j++)
            #pragma unroll
            for (int q = 0; q < 4; q++) acc[i][j][q] = 0.f;

    const int NC = K / BKH;

    auto load_stage = [&](int c) {
        const int s = c % GSTAGES;
        const uint32_t a_st = smem_base + s * STAGE2_H * 2;
        const uint32_t b_st = a_st + A_TILE_H * 2;
        const int kof = c * BKH;
        #pragma unroll
        for (int i = 0; i < 6; i++) {
            const int lin = tid + i * 512;
            if (lin < 2048) {
                const int r  = lin >> 3;
                const int cc = lin & 7;
                const uint32_t off = (uint32_t)(r * (SPH * 2) + cc * 16);
                cpa16(a_st + off, Abase + (size_t)r * K + kof + cc * 8);
            } else {
                const int j  = lin - 2048;
                const int r  = j >> 3;
                const int cc = j & 7;
                const uint32_t off = (uint32_t)(r * (SPH * 2) + cc * 16);
                cpa16(b_st + off, Bbase + (size_t)r * K + kof + cc * 8);
            }
        }
    };

    #pragma unroll
    for (int p = 0; p < GSTAGES - 1; p++) {
        load_stage(p);
        asm volatile("cp.async.commit_group;" ::: "memory");
    }

    for (int c = 0; c < NC; c++) {
        asm volatile("cp.async.wait_group %0;" :: "n"(GSTAGES - 2) : "memory");
        __syncthreads();

        if (c + GSTAGES - 1 < NC) load_stage(c + GSTAGES - 1);
        asm volatile("cp.async.commit_group;" ::: "memory");

        const uint32_t stage_base = smem_base + (c % GSTAGES) * STAGE2_H * 2;
        const uint32_t aAddr = stage_base + aOff;
        const uint32_t bAddr = stage_base + A_TILE_H * 2 + bOff;

        #pragma unroll
        for (int ks = 0; ks < 4; ks++) {
            uint32_t af[4][4], bf[4][2];
            #pragma unroll
            for (int im = 0; im < 4; im++)
                ldsm4(af[im][0], af[im][1], af[im][2], af[im][3],
                      aAddr + im * (16 * SPH * 2) + ks * 32);
            ldsm4(bf[0][0], bf[0][1], bf[1][0], bf[1][1], bAddr + ks * 32);
            ldsm4(bf[2][0], bf[2][1], bf[3][0], bf[3][1],
                  bAddr + 16 * SPH * 2 + ks * 32);
            #pragma unroll
            for (int im = 0; im < 4; im++)
                #pragma unroll
                for (int jn = 0; jn < 4; jn++)
                    mma_f16(acc[im][jn][0], acc[im][jn][1],
                            acc[im][jn][2], acc[im][jn][3],
                            af[im][0], af[im][1], af[im][2], af[im][3],
                            bf[jn][0], bf[jn][1]);
        }
    }

    // ---- epilogue (EPI_RES only) -------------------------------------------
    #pragma unroll
    for (int im = 0; im < 4; im++) {
        const int r0 = mrow0 + warpM * 64 + im * 16 + gi;
        #pragma unroll
        for (int hf = 0; hf < 2; hf++) {
            const size_t row = (size_t)(r0 + hf * 8);
            #pragma unroll
            for (int jn = 0; jn < 4; jn++) {
                const int col = ncol0 + warpN * 32 + jn * 8 + tig * 2;
                float ox = acc[im][jn][hf * 2 + 0];
                float oy = acc[im][jn][hf * 2 + 1];
                float2 bv = *(const float2*)(bias + col);
                ox += bv.x; oy += bv.y;
                float2 rv = *(const float2*)(res + row * N + col);
                float2 o2 = {ox + rv.x, oy + rv.y};
                *(float2*)((float*)Cv + row * N + col) = o2;
            }
        }
    }
}

// ------------------------- Flash attention (fp16 MMA) -----------------------
// 128 q-rows per CTA, 64-key tiles, double-buffered K/V. Q pre-scaled by 1/8.
// P stays in registers: S C-fragments repacked as P@V A-fragments.
#define KVH    (64 * SPH)
#define P_OFF  (4 * KVH)
#define ATTN_SMEM_B ((4 * KVH + 128 * SPH) * 2)   // 55296 B

__global__ void __launch_bounds__(256, 2) attn_kernel(
    const __half* __restrict__ qkv, const __half* __restrict__ vT,
    __half* __restrict__ out)
{
    extern __shared__ __half smh[];
    const uint32_t smem_base = smem_u32(smh);

    const int qt  = (int)gridDim.x - 1 - (int)blockIdx.x;  // heavy tiles first
    const int b   = blockIdx.y >> 4;
    const int h   = blockIdx.y & 15;
    const int tid = threadIdx.x;
    const int wid = tid >> 5;
    const int lane = tid & 31;
    const int gi  = lane >> 2;
    const int tig = lane & 3;

    const int q0 = qt * 128;
    const int qrow_w = q0 + wid * 16;
    const int nkt = qt * 2 + 2;

    const uint32_t nkOff = (uint32_t)(
        ((lane & 7) + ((lane >> 4) << 3)) * SPH
        + (((lane >> 3) & 1) << 3)) * 2;
    const uint32_t pOff = (uint32_t)(
        (wid * 16 + (lane & 7) + (((lane >> 3) & 1) << 3)) * SPH
        + ((lane >> 4) << 3)) * 2;

    auto load_tile = [&](int kt) {
        const int st = kt & 1;
        const __half* Kg = qkv + ((size_t)(b * SEQ + kt * 64)) * 3072
                           + DMODEL + h * HDIM;
        const __half* Vg = vT + ((size_t)((b * NHEADS + h) * HDIM)) * SEQ + kt * 64;
        const uint32_t Kd = smem_base + st * (KVH * 2);
        const uint32_t Vd = smem_base + (2 + st) * (KVH * 2);
        #pragma unroll
        for (int i = 0; i < 4; i++) {
            const int idx = tid + i * 256;
            if (idx < 512) {
                const int r = idx >> 3, cc = idx & 7;
                cpa16(Kd + r * (SPH * 2) + cc * 16, Kg + (size_t)r * 3072 + cc * 8);
            } else {
                const int j = idx - 512;
                const int r = j >> 3, cc = j & 7;
                cpa16(Vd + r * (SPH * 2) + cc * 16, Vg + (size_t)r * SEQ + cc * 8);
            }
        }
    };

    {
        const __half* Qg = qkv + ((size_t)(b * SEQ + q0)) * 3072 + h * HDIM;
        const uint32_t Pd = smem_base + P_OFF * 2;
        #pragma unroll
        for (int i = 0; i < 4; i++) {
            const int idx = tid + i * 256;
            const int r = idx >> 3, cc = idx & 7;
            cpa16(Pd + r * (SPH * 2) + cc * 16, Qg + (size_t)r * 3072 + cc * 8);
        }
        asm volatile("cp.async.commit_group;" ::: "memory");
        load_tile(0);
        asm volatile("cp.async.commit_group;" ::: "memory");
        asm volatile("cp.async.wait_group 0;" ::: "memory");
        __syncthreads();
    }

    uint32_t qf[4][4];
    {
        const uint32_t qAddr = smem_base + P_OFF * 2 + pOff;
        #pragma unroll
        for (int ks = 0; ks < 4; ks++)
            ldsm4(qf[ks][0], qf[ks][1], qf[ks][2], qf[ks][3], qAddr + ks * 32);
    }

    float m[2] = {-1e30f, -1e30f};
    float l[2] = {0.f, 0.f};
    float o[8][4];
    #pragma unroll
    for (int jn = 0; jn < 8; jn++)
        #pragma unroll
        for (int q = 0; q < 4; q++) o[jn][q] = 0.f;

    for (int kt = 0; kt < nkt; kt++) {
        if (kt > 0) {
            asm volatile("cp.async.wait_group 0;" ::: "memory");
            __syncthreads();
        }
        if (kt + 1 < nkt) {
            load_tile(kt + 1);
            asm volatile("cp.async.commit_group;" ::: "memory");
        }

        const int st = kt & 1;
        const uint32_t kAddr = smem_base + st * (KVH * 2) + nkOff;
        const uint32_t vAddr = smem_base + (2 + st) * (KVH * 2) + nkOff;

        // ---- S = (Q/8) @ K^T ----
        float s[8][4];
        #pragma unroll
        for (int jn = 0; jn < 8; jn++)
            #pragma unroll
            for (int q = 0; q < 4; q++) s[jn][q] = 0.f;

        #pragma unroll
        for (int ks = 0; ks < 4; ks++) {
            uint32_t bf[8][2];
            #pragma unroll
            for (int jnp = 0; jnp < 4; jnp++)
                ldsm4(bf[2 * jnp][0], bf[2 * jnp][1],
                      bf[2 * jnp + 1][0], bf[2 * jnp + 1][1],
                      kAddr + jnp * (16 * SPH * 2) + ks * 32);
            #pragma unroll
            for (int jn = 0; jn < 8; jn++)
                mma_f16(s[jn][0], s[jn][1], s[jn][2], s[jn][3],
                        qf[ks][0], qf[ks][1], qf[ks][2], qf[ks][3],
                        bf[jn][0], bf[jn][1]);
        }

        if (kt * 64 + 63 > qrow_w) {
            #pragma unroll
            for (int jn = 0; jn < 8; jn++) {
                const int kc = kt * 64 + jn * 8 + tig * 2;
                const int r0 = qrow_w + gi;
                const int r1 = r0 + 8;
                if (kc     > r0) s[jn][0] = -1e30f;
                if (kc + 1 > r0) s[jn][1] = -1e30f;
                if (kc     > r1) s[jn][2] = -1e30f;
                if (kc + 1 > r1) s[jn][3] = -1e30f;
            }
        }

        #pragma unroll
        for (int rr = 0; rr < 2; rr++) {
            const int i0 = rr * 2, i1 = rr * 2 + 1;
            float mx = -1e30f;
            #pragma unroll
            for (int jn = 0; jn < 8; jn++)
                mx = fmaxf(mx, fmaxf(s[jn][i0], s[jn][i1]));
            mx = fmaxf(mx, __shfl_xor_sync(0xffffffffu, mx, 1));
            mx = fmaxf(mx, __shfl_xor_sync(0xffffffffu, mx, 2));
            const float mn = fmaxf(m[rr], mx);
            const float al = __expf(m[rr] - mn);
            float rs = 0.f;
            #pragma unroll
            for (int jn = 0; jn < 8; jn++) {
                const float e0 = __expf(s[jn][i0] - mn);
                const float e1 = __expf(s[jn][i1] - mn);
                s[jn][i0] = e0; s[jn][i1] = e1;
                rs += e0 + e1;
            }
            rs += __shfl_xor_sync(0xffffffffu, rs, 1);
            rs += __shfl_xor_sync(0xffffffffu, rs, 2);
            l[rr] = l[rr] * al + rs;
            m[rr] = mn;
            #pragma unroll
            for (int jn = 0; jn < 8; jn++) { o[jn][i0] *= al; o[jn][i1] *= al; }
        }

        // ---- O += P @ V : P fragments packed directly from S registers ----
        // A-frag for keys 16ks..16ks+15:
        //   a0 = P[gi][16ks+2tig..+1]      = s[2ks][0..1]
        //   a1 = P[gi+8][16ks+2tig..+1]    = s[2ks][2..3]
        //   a2 = P[gi][16ks+8+2tig..+1]    = s[2ks+1][0..1]
        //   a3 = P[gi+8][16ks+8+2tig..+1]  = s[2ks+1][2..3]
        #pragma unroll
        for (int ks = 0; ks < 4; ks++) {
            __half2 a0h = __floats2half2_rn(s[2 * ks][0],     s[2 * ks][1]);
            __half2 a1h = __floats2half2_rn(s[2 * ks][2],     s[2 * ks][3]);
            __half2 a2h = __floats2half2_rn(s[2 * ks + 1][0], s[2 * ks + 1][1]);
            __half2 a3h = __floats2half2_rn(s[2 * ks + 1][2], s[2 * ks + 1][3]);
            const uint32_t a0 = *(uint32_t*)&a0h;
            const uint32_t a1 = *(uint32_t*)&a1h;
            const uint32_t a2 = *(uint32_t*)&a2h;
            const uint32_t a3 = *(uint32_t*)&a3h;
            uint32_t vf[8][2];
            #pragma unroll
            for (int jnp = 0; jnp < 4; jnp++)
                ldsm4(vf[2 * jnp][0], vf[2 * jnp][1],
                      vf[2 * jnp + 1][0], vf[2 * jnp + 1][1],
                      vAddr + jnp * (16 * SPH * 2) + ks * 32);
            #pragma unroll
            for (int jn = 0; jn < 8; jn++)
                mma_f16(o[jn][0], o[jn][1], o[jn][2], o[jn][3],
                        a0, a1, a2, a3, vf[jn][0], vf[jn][1]);
        }
    }

    const float inv0 = 1.0f / l[0];
    const float inv1 = 1.0f / l[1];
    __half* O0 = out + ((size_t)(b * SEQ) + qrow_w + gi)     * DMODEL + h * HDIM;
    __half* O1 = out + ((size_t)(b * SEQ) + qrow_w + gi + 8) * DMODEL + h * HDIM;
    #pragma unroll
    for (int jn = 0; jn < 8; jn++) {
        __half2 v0 = __floats2half2_rn(o[jn][0] * inv0, o[jn][1] * inv0);
        __half2 v1 = __floats2half2_rn(o[jn][2] * inv1, o[jn][3] * inv1);
        *(__half2*)(O0 + jn * 8 + tig * 2) = v0;
        *(__half2*)(O1 + jn * 8 + tig * 2) = v1;
    }
}

// ------------------------------- launcher -----------------------------------
extern "C" void kernel_launch(void* const* d_in, const int* in_sizes, int n_in,
                              void* d_out, int out_size)
{
    const float* hidden = (const float*)d_in[0];
    const float* w_qkv  = (const float*)d_in[1];
    const float* b_qkv  = (const float*)d_in[2];
    const float* g1     = (const float*)d_in[3];
    const float* be1    = (const float*)d_in[4];
    const float* w_proj = (const float*)d_in[5];
    const float* b_proj = (const float*)d_in[6];
    const float* g2     = (const float*)d_in[7];
    const float* be2    = (const float*)d_in[8];
    const float* w_fc   = (const float*)d_in[9];
    const float* b_fc   = (const float*)d_in[10];
    const float* w_mlp  = (const float*)d_in[11];
    const float* b_mlp  = (const float*)d_in[12];
    float* out = (float*)d_out;

    __half *x, *qkv, *vT, *attn, *y, *fc, *wT;
    float  *h2;
    cudaGetSymbolAddress((void**)&x,    g_x);
    cudaGetSymbolAddress((void**)&qkv,  g_qkv);
    cudaGetSymbolAddress((void**)&vT,   g_vT);
    cudaGetSymbolAddress((void**)&attn, g_attn);
    cudaGetSymbolAddress((void**)&h2,   g_h2);
    cudaGetSymbolAddress((void**)&y,    g_y);
    cudaGetSymbolAddress((void**)&fc,   g_fc);
    cudaGetSymbolAddress((void**)&wT,   g_wT);

    __half* wT_qkv  = wT + WT_QKV_OFF;
    __half* wT_proj = wT + WT_PROJ_OFF;
    __half* wT_fc   = wT + WT_FC_OFF;
    __half* wT_mlp  = wT + WT_MLP_OFF;

    cudaFuncSetAttribute(attn_kernel,
                         cudaFuncAttributeMaxDynamicSharedMemorySize, ATTN_SMEM_B);
    cudaFuncSetAttribute(hgemm_kernel<EPI_QKV>,
                         cudaFuncAttributeMaxDynamicSharedMemorySize, GSMEM_DYN);
    cudaFuncSetAttribute(hgemm_kernel<EPI_GELU>,
                         cudaFuncAttributeMaxDynamicSharedMemorySize, GSMEM_DYN);
    cudaFuncSetAttribute(hgemm256_kernel<EPI_RES>,
                         cudaFuncAttributeMaxDynamicSharedMemorySize, GSMEM2_DYN);

    // 1. prep: LN1 + all 4 weight transposes in one launch
    prep_kernel<<<ROWS + 12288, 256>>>(hidden, g1, be1, x,
                                       w_qkv, w_proj, w_fc, w_mlp, wT);
    // 2. QKV (Q pre-scaled 1/8; K -> qkv half; V -> vT transposed)
    hgemm_kernel<EPI_QKV><<<dim3(3 * DMODEL / 128, ROWS / 128), 512, GSMEM_DYN>>>(
        x, wT_qkv, b_qkv, nullptr, qkv, vT, ROWS, 3 * DMODEL, DMODEL);
    // 3. attention -> half
    attn_kernel<<<dim3(SEQ / 128, BATCH * NHEADS), 256, ATTN_SMEM_B>>>(qkv, vT, attn);
    // 4. h2 = attn @ w_proj + b_proj + hidden  (f32)  [256-row tiles]
    hgemm256_kernel<EPI_RES><<<dim3(DMODEL / 128, ROWS / 256), 512, GSMEM2_DYN>>>(
        attn, wT_proj, b_proj, hidden, h2, ROWS, DMODEL, DMODEL);
    // 5. LN2 -> half
    ln_kernel<<<ROWS, 256>>>(h2, g2, be2, y);
    // 6. fc = gelu(y @ w_fc + b_fc) -> half
    hgemm_kernel<EPI_GELU><<<dim3(INNER / 128, ROWS / 128), 512, GSMEM_DYN>>>(
        y, wT_fc, b_fc, nullptr, fc, nullptr, ROWS, INNER, DMODEL);
    // 7. out = fc @ w_mlp + b_mlp + h2  (f32)  [256-row tiles]
    hgemm256_kernel<EPI_RES><<<dim3(DMODEL / 128, ROWS / 256), 512, GSMEM2_DYN>>>(
        fc, wT_mlp, b_mlp, h2, out, ROWS, DMODEL, INNER);
}